// round 7
// baseline (speedup 1.0000x reference)
#include <cuda_runtime.h>
#include <math.h>

#define NSTMT 100000
#define NFUNC 50000
#define NTOT  150000
#define CDIM  128
#define NH    8
#define HD    16
#define NE    200000
#define NTOK  16
#define CC    (CDIM*CDIM)

typedef unsigned long long ull;

// ---------------- scratch (static device globals; no allocation) ----------------
__device__ __align__(16) float g_q[(size_t)NTOT*CDIM];                // raw q
__device__ __align__(16) float g_k[(size_t)NTOT*CDIM];                // raw k
__device__ __align__(16) float g_v[(size_t)NTOT*CDIM];                // raw v
__device__ __align__(16) float g_qr[(size_t)(2*NSTMT+NFUNC)*CDIM];    // a_rel-transformed q per relation
__device__ __align__(16) float g_agg[(size_t)NTOT*CDIM];              // agg r0(stmt) + r1(func)
__device__ __align__(16) float g_agg2[(size_t)NSTMT*CDIM];            // agg r2 (stmt)
__device__ __align__(16) float g_s[(size_t)3*NSTMT*NH];               // softmax denominators
__device__ __align__(16) float g_p2[(size_t)NTOT*CDIM];               // pooled / epilogue-prep

// ---------------- helpers ----------------
__device__ __forceinline__ float gelu_f(float x) {
    float x3 = x*x*x;
    return 0.5f*x*(1.0f + tanhf(0.7978845608028654f*(x + 0.044715f*x3)));
}
__device__ __forceinline__ void fma2(ull& c, ull a, ull b) {
    asm("fma.rn.f32x2 %0, %1, %2, %0;" : "+l"(c) : "l"(a), "l"(b));
}
__device__ __forceinline__ ull pack2dup(float x) {
    ull r; unsigned u = __float_as_uint(x);
    asm("mov.b64 %0, {%1, %2};" : "=l"(r) : "r"(u), "r"(u));
    return r;
}
__device__ __forceinline__ float2 unpack2(ull v) {
    unsigned lo, hi;
    asm("mov.b64 {%0, %1}, %2;" : "=r"(lo), "=r"(hi) : "l"(v));
    return make_float2(__uint_as_float(lo), __uint_as_float(hi));
}

// ---------------- GEMM: 128x128 tile, 256 thr, double-buffered, reg-pipelined ----------------
// EPI: 0 relu; 1 none; 2 blend g*v+(1-g)*xold. Slab selected by blockIdx.y.
struct Slabs { const float* W[3]; const float* B[3]; float* O[3]; };

template<int EPI>
__global__ __launch_bounds__(256, 2) void gemm_k(
    const float* __restrict__ A, Slabs sl, int M,
    const float* __restrict__ xold, const float* __restrict__ skipv) {
    __shared__ float As[2][16][128];
    __shared__ float Ws[2][16][128];
    const int tid = threadIdx.x;
    const int row0 = blockIdx.x * 128;
    const float* __restrict__ W = sl.W[blockIdx.y];
    const float* __restrict__ bias = sl.B[blockIdx.y];
    float* __restrict__ out = sl.O[blockIdx.y];

    const int lr = tid >> 1;
    const int lk = (tid & 1) * 8;
    const int wk = tid >> 4;
    const int wc = (tid & 15) * 8;
    const int ty = tid >> 4;
    const int tx = tid & 15;

    const int  arow = row0 + lr;
    const bool aval = arow < M;
    const float* Ap = A + (size_t)arow * CDIM + lk;
    const float* Wp = W + (size_t)wk * CDIM + wc;

    ull acc[8][4];
#pragma unroll
    for (int i = 0; i < 8; i++)
#pragma unroll
        for (int j = 0; j < 4; j++) acc[i][j] = 0ull;

    float4 ga0, ga1, gw0, gw1;
    const float4 z4 = make_float4(0.f, 0.f, 0.f, 0.f);

    auto loadG = [&](int s) {
        ga0 = z4; ga1 = z4;
        if (aval) {
            ga0 = *reinterpret_cast<const float4*>(Ap + s*16);
            ga1 = *reinterpret_cast<const float4*>(Ap + s*16 + 4);
        }
        gw0 = *reinterpret_cast<const float4*>(Wp + (size_t)s*16*CDIM);
        gw1 = *reinterpret_cast<const float4*>(Wp + (size_t)s*16*CDIM + 4);
    };
    auto storeS = [&](int buf) {
        As[buf][lk+0][lr] = ga0.x; As[buf][lk+1][lr] = ga0.y;
        As[buf][lk+2][lr] = ga0.z; As[buf][lk+3][lr] = ga0.w;
        As[buf][lk+4][lr] = ga1.x; As[buf][lk+5][lr] = ga1.y;
        As[buf][lk+6][lr] = ga1.z; As[buf][lk+7][lr] = ga1.w;
        *reinterpret_cast<float4*>(&Ws[buf][wk][wc])     = gw0;
        *reinterpret_cast<float4*>(&Ws[buf][wk][wc + 4]) = gw1;
    };

    float a0[8], a1[8];
    ull   b0[4], b1[4];
    auto ldA = [&](float* a, int buf, int k) {
        *reinterpret_cast<float4*>(a)     = *reinterpret_cast<const float4*>(&As[buf][k][ty*8]);
        *reinterpret_cast<float4*>(a + 4) = *reinterpret_cast<const float4*>(&As[buf][k][ty*8 + 4]);
    };
    auto ldB = [&](ull* b, int buf, int k) {
        *reinterpret_cast<ulonglong2*>(b)     = *reinterpret_cast<const ulonglong2*>(&Ws[buf][k][tx*8]);
        *reinterpret_cast<ulonglong2*>(b + 2) = *reinterpret_cast<const ulonglong2*>(&Ws[buf][k][tx*8 + 4]);
    };
    auto dofma = [&](const float* a, const ull* b) {
#pragma unroll
        for (int i = 0; i < 8; i++) {
            ull aa = pack2dup(a[i]);
#pragma unroll
            for (int j = 0; j < 4; j++) fma2(acc[i][j], aa, b[j]);
        }
    };

    loadG(0);
    storeS(0);
    __syncthreads();

#pragma unroll 1
    for (int s = 0; s < 8; s++) {
        const int cur = s & 1;
        if (s < 7) loadG(s + 1);
        ldA(a0, cur, 0); ldB(b0, cur, 0);
#pragma unroll
        for (int k = 0; k < 16; k++) {
            if (k & 1) {
                if (k < 15) { ldA(a0, cur, k + 1); ldB(b0, cur, k + 1); }
                dofma(a1, b1);
            } else {
                if (k < 15) { ldA(a1, cur, k + 1); ldB(b1, cur, k + 1); }
                dofma(a0, b0);
            }
        }
        if (s < 7) {
            storeS(cur ^ 1);
            __syncthreads();
        }
    }

    float g = 0.f, og = 0.f;
    if (EPI == 2) { g = 1.0f/(1.0f + expf(-*skipv)); og = 1.0f - g; }
    float2 bb[4];
#pragma unroll
    for (int j = 0; j < 4; j++) bb[j] = *reinterpret_cast<const float2*>(&bias[tx*8 + 2*j]);

#pragma unroll
    for (int i = 0; i < 8; i++) {
        int row = row0 + ty*8 + i;
        if (row >= M) continue;
        float* orow = out + (size_t)row*CDIM + tx*8;
        const float* xrow = (EPI == 2) ? (xold + (size_t)row*CDIM + tx*8) : nullptr;
#pragma unroll
        for (int jj = 0; jj < 2; jj++) {
            float2 p0 = unpack2(acc[i][2*jj]);
            float2 p1 = unpack2(acc[i][2*jj + 1]);
            float4 v = make_float4(p0.x + bb[2*jj].x,   p0.y + bb[2*jj].y,
                                   p1.x + bb[2*jj+1].x, p1.y + bb[2*jj+1].y);
            if (EPI == 0) {
                v.x = fmaxf(v.x, 0.f); v.y = fmaxf(v.y, 0.f);
                v.z = fmaxf(v.z, 0.f); v.w = fmaxf(v.w, 0.f);
            }
            if (EPI == 2) {
                float4 xo = *reinterpret_cast<const float4*>(xrow + 4*jj);
                v.x = g*v.x + og*xo.x; v.y = g*v.y + og*xo.y;
                v.z = g*v.z + og*xo.z; v.w = g*v.w + og*xo.w;
            }
            *reinterpret_cast<float4*>(orow + 4*jj) = v;
        }
    }
}

// ---------------- small kernels ----------------
__global__ void fill_k(float* p, float val, int n) {
    int i = blockIdx.x*blockDim.x + threadIdx.x;
    if (i < n) p[i] = val;
}

// embedding gather + mean + relu (fp32 out)
__global__ void pool_k(const int* __restrict__ tok, const float* __restrict__ emb,
                       float* __restrict__ out, int N) {
    int node = blockIdx.x*2 + (threadIdx.x >> 7);
    int c = threadIdx.x & 127;
    if (node >= N) return;
    const int* tp = tok + (size_t)node*NTOK;
    float s = 0.f;
#pragma unroll
    for (int t = 0; t < NTOK; t++) s += emb[(size_t)tp[t]*CDIM + c];
    s *= (1.0f/NTOK);
    out[(size_t)node*CDIM + c] = s > 0.f ? s : 0.f;
}

// qr[n, h, d] = (p_rel[h]*scale) * sum_e a_rel[h][d][e] * q[n, h, e]   (per relation)
__global__ void qr_k(const float* __restrict__ q, const float* __restrict__ a_rel,
                     const float* __restrict__ p_rel, float* __restrict__ qr, int l) {
    const int r = blockIdx.y;
    const int N = (r == 1) ? NFUNC : NSTMT;
    const float* qs = q + ((r == 1) ? (size_t)NSTMT*CDIM : 0);
    float* out = qr + ((r == 0) ? 0 : (r == 1) ? (size_t)NSTMT*CDIM
                                               : (size_t)(NSTMT+NFUNC)*CDIM);
    __shared__ float At[NH*HD*HD];   // transposed: At[h][e][d]
    __shared__ float ps[NH];
    const int tid = threadIdx.x;
    const float* Ag = a_rel + (size_t)(l*3 + r)*NH*HD*HD;
    for (int i = tid; i < NH*HD*HD; i += 256) {
        int h = i >> 8, d = (i >> 4) & 15, e = i & 15;
        At[(h << 8) + (e << 4) + d] = Ag[i];
    }
    if (tid < NH) ps[tid] = p_rel[(l*3 + r)*NH + tid] * 0.25f;
    __syncthreads();

    int node = blockIdx.x*2 + (tid >> 7);
    if (node >= N) return;
    int c = tid & 127;
    int h = c >> 4, d = c & 15;
    const float* qrow = qs + (size_t)node*CDIM + h*HD;
    const float* Ah = At + (h << 8) + d;
    float sum = 0.f;
#pragma unroll
    for (int e = 0; e < HD; e++) sum += Ah[e << 4] * __ldg(qrow + e);
    out[(size_t)node*CDIM + c] = sum * ps[h];
}

// epilogue prep: P[n,h,e] = gelu( sum_r (1/s_r) * sum_d agg_r[n,h,d] * M_r[h][d][e] )
template<int NR>
__global__ void aggprep_k(const float* __restrict__ agg0, const float* __restrict__ agg2,
                          const float* __restrict__ s0, const float* __restrict__ s2,
                          const float* __restrict__ M0g, const float* __restrict__ M2g,
                          float* __restrict__ P, int N) {
    __shared__ float M0[NH*HD*HD];   // M[h][d][e] — e contiguous, conflict-free
    __shared__ float M2[NH*HD*HD];
    const int tid = threadIdx.x;
    for (int i = tid; i < NH*HD*HD; i += 256) {
        M0[i] = M0g[i];
        if (NR == 2) M2[i] = M2g[i];
    }
    __syncthreads();

    int node = blockIdx.x*2 + (tid >> 7);
    if (node >= N) return;
    int c = tid & 127;
    int h = c >> 4, e = c & 15;
    const float* a0 = agg0 + (size_t)node*CDIM + h*HD;
    float w0 = 1.0f / (s0[(size_t)node*NH + h] + 1e-16f);
    float t0 = 0.f;
#pragma unroll
    for (int d = 0; d < HD; d++) t0 += __ldg(a0 + d) * M0[(h << 8) + (d << 4) + e];
    float v = t0 * w0;
    if (NR == 2) {
        const float* a2 = agg2 + (size_t)node*CDIM + h*HD;
        float w2 = 1.0f / (s2[(size_t)node*NH + h] + 1e-16f);
        float t2 = 0.f;
#pragma unroll
        for (int d = 0; d < HD; d++) t2 += __ldg(a2 + d) * M2[(h << 8) + (d << 4) + e];
        v += t2 * w2;
    }
    P[(size_t)node*CDIM + c] = gelu_f(v);
}

// ---------------- fused edge kernel (all 3 relations via blockIdx.y) ----------------
// p = exp(dot(qr[dst], k[src])); s[dst,h] += p; agg_r[dst] += p * v[src]
struct EdgeArgs {
    const int*   src[3];
    const int*   dst[3];
    const float* qr[3];
    const float* k[3];
    const float* v[3];
    float*       sb[3];
    float*       agg[3];
};

__global__ void edge_k(EdgeArgs ea, int ne) {
    int e = (blockIdx.x*blockDim.x + threadIdx.x) >> 5;
    int lane = threadIdx.x & 31;
    if (e >= ne) return;
    int r = blockIdx.y;
    int s = ea.src[r][e], d = ea.dst[r][e];
    float4 qv = *reinterpret_cast<const float4*>(ea.qr[r] + (size_t)d*CDIM + lane*4);
    float4 kv = *reinterpret_cast<const float4*>(ea.k[r]  + (size_t)s*CDIM + lane*4);
    float p = qv.x*kv.x + qv.y*kv.y + qv.z*kv.z + qv.w*kv.w;
    p += __shfl_xor_sync(0xffffffffu, p, 1);
    p += __shfl_xor_sync(0xffffffffu, p, 2);
    float ev = __expf(p);
    int h = lane >> 2;
    if ((lane & 3) == 0) atomicAdd(ea.sb[r] + (size_t)d*NH + h, ev);
    float4 v = *reinterpret_cast<const float4*>(ea.v[r] + (size_t)s*CDIM + lane*4);
    v.x *= ev; v.y *= ev; v.z *= ev; v.w *= ev;
    atomicAdd(reinterpret_cast<float4*>(ea.agg[r] + (size_t)d*CDIM + lane*4), v);
}

// ---------------- host launcher ----------------
static inline int GB(int m) { return (m + 127) / 128; }

extern "C" void kernel_launch(void* const* d_in, const int* in_sizes, int n_in,
                              void* d_out, int out_size) {
    const int* tok_stmt = (const int*)d_in[0];
    const int* tok_func = (const int*)d_in[1];
    const int* esrc[3] = {(const int*)d_in[2], (const int*)d_in[4], (const int*)d_in[6]};
    const int* edst[3] = {(const int*)d_in[3], (const int*)d_in[5], (const int*)d_in[7]};
    const float* emb   = (const float*)d_in[8];
    const float* lin_w = (const float*)d_in[9];
    const float* lin_b = (const float*)d_in[10];
    const float* kw = (const float*)d_in[11];
    const float* kb = (const float*)d_in[12];
    const float* qw = (const float*)d_in[13];
    const float* qb = (const float*)d_in[14];
    const float* vw = (const float*)d_in[15];
    const float* vb = (const float*)d_in[16];
    const float* aw = (const float*)d_in[17];
    const float* ab = (const float*)d_in[18];
    const float* skip  = (const float*)d_in[19];
    const float* a_rel = (const float*)d_in[20];
    const float* m_rel = (const float*)d_in[21];
    const float* p_rel = (const float*)d_in[22];
    float* x = (float*)d_out;

    float *q, *k, *v, *qr, *agg, *agg2, *sbuf, *p2;
    cudaGetSymbolAddress((void**)&q,    g_q);
    cudaGetSymbolAddress((void**)&k,    g_k);
    cudaGetSymbolAddress((void**)&v,    g_v);
    cudaGetSymbolAddress((void**)&qr,   g_qr);
    cudaGetSymbolAddress((void**)&agg,  g_agg);
    cudaGetSymbolAddress((void**)&agg2, g_agg2);
    cudaGetSymbolAddress((void**)&sbuf, g_s);
    cudaGetSymbolAddress((void**)&p2,   g_p2);

    const size_t XF = (size_t)NSTMT*CDIM;

    // ---- encoder: pool + per-type linear + relu ----
    pool_k<<<(NSTMT+1)/2, 256>>>(tok_stmt, emb, p2, NSTMT);
    pool_k<<<(NFUNC+1)/2, 256>>>(tok_func, emb, p2 + XF, NFUNC);
    {
        Slabs s{}; s.W[0] = lin_w; s.B[0] = lin_b; s.O[0] = x;
        gemm_k<0><<<dim3(GB(NSTMT),1), 256>>>(p2, s, NSTMT, nullptr, nullptr);
        Slabs f{}; f.W[0] = lin_w + CC; f.B[0] = lin_b + CDIM; f.O[0] = x + XF;
        gemm_k<0><<<dim3(GB(NFUNC),1), 256>>>(p2 + XF, f, NFUNC, nullptr, nullptr);
    }

    for (int l = 0; l < 2; l++) {
        // raw projections q/k/v for both types (slab over 3 weights)
        {
            Slabs s{};
            s.W[0] = qw + (size_t)(l*2+0)*CC; s.B[0] = qb + (size_t)(l*2+0)*CDIM; s.O[0] = q;
            s.W[1] = kw + (size_t)(l*2+0)*CC; s.B[1] = kb + (size_t)(l*2+0)*CDIM; s.O[1] = k;
            s.W[2] = vw + (size_t)(l*2+0)*CC; s.B[2] = vb + (size_t)(l*2+0)*CDIM; s.O[2] = v;
            gemm_k<1><<<dim3(GB(NSTMT),3), 256>>>(x, s, NSTMT, nullptr, nullptr);
            Slabs f{};
            f.W[0] = qw + (size_t)(l*2+1)*CC; f.B[0] = qb + (size_t)(l*2+1)*CDIM; f.O[0] = q + XF;
            f.W[1] = kw + (size_t)(l*2+1)*CC; f.B[1] = kb + (size_t)(l*2+1)*CDIM; f.O[1] = k + XF;
            f.W[2] = vw + (size_t)(l*2+1)*CC; f.B[2] = vb + (size_t)(l*2+1)*CDIM; f.O[2] = v + XF;
            gemm_k<1><<<dim3(GB(NFUNC),3), 256>>>(x + XF, f, NFUNC, nullptr, nullptr);
        }

        // qr = a_rel^T q (dst side), p_rel*scale folded
        qr_k<<<dim3((NSTMT+1)/2, 3), 256>>>(q, a_rel, p_rel, qr, l);

        fill_k<<<((int)(NTOT*(size_t)CDIM) + 255)/256, 256>>>(agg, 0.f, NTOT*CDIM);
        fill_k<<<((int)(NSTMT*(size_t)CDIM) + 255)/256, 256>>>(agg2, 0.f, NSTMT*CDIM);
        fill_k<<<(3*NSTMT*NH + 255)/256, 256>>>(sbuf, 0.f, 3*NSTMT*NH);

        EdgeArgs ea;
        const float* qroff[3] = {qr, qr + XF, qr + XF + (size_t)NFUNC*CDIM};
        for (int r = 0; r < 3; r++) {
            ea.src[r] = esrc[r]; ea.dst[r] = edst[r];
            ea.qr[r] = qroff[r];
            ea.k[r] = k + ((r == 2) ? XF : 0);   // src type: stmt,stmt,func
            ea.v[r] = v + ((r == 2) ? XF : 0);
            ea.sb[r] = sbuf + (size_t)r*NSTMT*NH;
        }
        ea.agg[0] = agg;          // rel0 -> stmt
        ea.agg[1] = agg + XF;     // rel1 -> func
        ea.agg[2] = agg2;         // rel2 -> stmt
        edge_k<<<dim3((NE*32 + 255)/256, 3), 256>>>(ea, NE);

        // epilogue prep: P = gelu( sum_r m_rel_r . agg_r / s_r )
        const float* M0 = m_rel + (size_t)(l*3 + 0)*NH*HD*HD;
        const float* M1 = m_rel + (size_t)(l*3 + 1)*NH*HD*HD;
        const float* M2 = m_rel + (size_t)(l*3 + 2)*NH*HD*HD;
        aggprep_k<2><<<(NSTMT+1)/2, 256>>>(agg, agg2,
            sbuf + 0*(size_t)NSTMT*NH, sbuf + 2*(size_t)NSTMT*NH, M0, M2, p2, NSTMT);
        aggprep_k<1><<<(NFUNC+1)/2, 256>>>(agg + XF, nullptr,
            sbuf + 1*(size_t)NSTMT*NH, nullptr, M1, nullptr, p2 + XF, NFUNC);

        // epilogue: x = g*(P @ aw + ab) + (1-g)*x
        {
            Slabs s{}; s.W[0] = aw + (size_t)(l*2+0)*CC; s.B[0] = ab + (size_t)(l*2+0)*CDIM; s.O[0] = x;
            gemm_k<2><<<dim3(GB(NSTMT),1), 256>>>(p2, s, NSTMT, x, skip + l*2 + 0);
            Slabs f{}; f.W[0] = aw + (size_t)(l*2+1)*CC; f.B[0] = ab + (size_t)(l*2+1)*CDIM; f.O[0] = x + XF;
            gemm_k<2><<<dim3(GB(NFUNC),1), 256>>>(p2 + XF, f, NFUNC, x + XF, skip + l*2 + 1);
        }
    }
}

// round 8
// speedup vs baseline: 2.0103x; 2.0103x over previous
#include <cuda_runtime.h>
#include <math.h>

#define NSTMT 100000
#define NFUNC 50000
#define NTOT  150000
#define CDIM  128
#define NH    8
#define HD    16
#define NE    200000
#define NTOK  16
#define CC    (CDIM*CDIM)

typedef unsigned long long ull;

// ---------------- scratch (static device globals; no allocation) ----------------
__device__ __align__(16) float g_q[(size_t)NTOT*CDIM];                // raw q
__device__ __align__(16) float g_k[(size_t)NTOT*CDIM];                // raw k
__device__ __align__(16) float g_v[(size_t)NTOT*CDIM];                // raw v
__device__ __align__(16) float g_qr[(size_t)(2*NSTMT+NFUNC)*CDIM];    // a_rel-transformed q per relation
__device__ __align__(16) float g_agg[(size_t)NTOT*CDIM];              // agg r0(stmt) + r1(func)
__device__ __align__(16) float g_agg2[(size_t)NSTMT*CDIM];            // agg r2 (stmt)
__device__ __align__(16) float g_s[(size_t)3*NSTMT*NH];               // softmax denominators
__device__ __align__(16) float g_p2[(size_t)NTOT*CDIM];               // pooled / epilogue-prep

// ---------------- helpers ----------------
__device__ __forceinline__ float gelu_f(float x) {
    float x3 = x*x*x;
    return 0.5f*x*(1.0f + tanhf(0.7978845608028654f*(x + 0.044715f*x3)));
}
__device__ __forceinline__ void fma2(ull& c, ull a, ull b) {
    asm("fma.rn.f32x2 %0, %1, %2, %0;" : "+l"(c) : "l"(a), "l"(b));
}
__device__ __forceinline__ ull pack2dup(float x) {
    ull r; unsigned u = __float_as_uint(x);
    asm("mov.b64 %0, {%1, %2};" : "=l"(r) : "r"(u), "r"(u));
    return r;
}
__device__ __forceinline__ float2 unpack2(ull v) {
    unsigned lo, hi;
    asm("mov.b64 {%0, %1}, %2;" : "=r"(lo), "=r"(hi) : "l"(v));
    return make_float2(__uint_as_float(lo), __uint_as_float(hi));
}

// ---------------- GEMM: R2-proven core. 128x128 tile, 256 thr, single-buffer 16-deep,
// register prefetch of next stage. Slab via blockIdx.y. EPI: 0 relu; 1 none; 2 blend.
struct Slabs { const float* W[3]; const float* B[3]; float* O[3]; };

template<int EPI>
__global__ __launch_bounds__(256) void gemm_k(
    const float* __restrict__ A, Slabs sl, int M,
    const float* __restrict__ xold, const float* __restrict__ skipv) {
    __shared__ float As[16][128];
    __shared__ float Ws[16][128];
    const int tid  = threadIdx.x;
    const int row0 = blockIdx.x * 128;
    const float* __restrict__ W = sl.W[blockIdx.y];
    const float* __restrict__ bias = sl.B[blockIdx.y];
    float* __restrict__ out = sl.O[blockIdx.y];

    const int lr  = tid >> 1;
    const int lkq = (tid & 1) * 8;
    const int wk  = tid >> 4;
    const int wc  = (tid & 15) * 8;
    const int ty  = tid >> 4;
    const int tx  = tid & 15;

    const int  arow = row0 + lr;
    const bool aval = arow < M;
    const float* Ap = A + (size_t)arow * CDIM + lkq;
    const float* Wp = W + (size_t)wk * CDIM + wc;

    ull acc[8][4];
#pragma unroll
    for (int i = 0; i < 8; i++)
#pragma unroll
        for (int j = 0; j < 4; j++) acc[i][j] = 0ull;

    float4 pa0, pa1, pw0, pw1;
    const float4 z4 = make_float4(0.f, 0.f, 0.f, 0.f);

    // fetch stage 0
    pa0 = aval ? *reinterpret_cast<const float4*>(Ap)     : z4;
    pa1 = aval ? *reinterpret_cast<const float4*>(Ap + 4) : z4;
    pw0 = *reinterpret_cast<const float4*>(Wp);
    pw1 = *reinterpret_cast<const float4*>(Wp + 4);

#pragma unroll 1
    for (int s = 0; s < 8; s++) {
        As[lkq+0][lr] = pa0.x; As[lkq+1][lr] = pa0.y; As[lkq+2][lr] = pa0.z; As[lkq+3][lr] = pa0.w;
        As[lkq+4][lr] = pa1.x; As[lkq+5][lr] = pa1.y; As[lkq+6][lr] = pa1.z; As[lkq+7][lr] = pa1.w;
        *reinterpret_cast<float4*>(&Ws[wk][wc])     = pw0;
        *reinterpret_cast<float4*>(&Ws[wk][wc + 4]) = pw1;
        __syncthreads();

        if (s < 7) {
            int k0 = (s + 1) * 16;
            pa0 = aval ? *reinterpret_cast<const float4*>(Ap + k0)     : z4;
            pa1 = aval ? *reinterpret_cast<const float4*>(Ap + k0 + 4) : z4;
            pw0 = *reinterpret_cast<const float4*>(Wp + (size_t)k0 * CDIM);
            pw1 = *reinterpret_cast<const float4*>(Wp + (size_t)k0 * CDIM + 4);
        }

#pragma unroll
        for (int k = 0; k < 16; k++) {
            float a[8]; ull bp[4];
            *reinterpret_cast<float4*>(a)     = *reinterpret_cast<const float4*>(&As[k][ty*8]);
            *reinterpret_cast<float4*>(a + 4) = *reinterpret_cast<const float4*>(&As[k][ty*8 + 4]);
            *reinterpret_cast<ulonglong2*>(bp)     = *reinterpret_cast<const ulonglong2*>(&Ws[k][tx*8]);
            *reinterpret_cast<ulonglong2*>(bp + 2) = *reinterpret_cast<const ulonglong2*>(&Ws[k][tx*8 + 4]);
#pragma unroll
            for (int i = 0; i < 8; i++) {
                ull aa = pack2dup(a[i]);
#pragma unroll
                for (int j = 0; j < 4; j++) fma2(acc[i][j], aa, bp[j]);
            }
        }
        if (s < 7) __syncthreads();
    }

    float g = 0.f, og = 0.f;
    if (EPI == 2) { g = 1.0f/(1.0f + expf(-*skipv)); og = 1.0f - g; }
    float2 bb[4];
#pragma unroll
    for (int j = 0; j < 4; j++) bb[j] = *reinterpret_cast<const float2*>(&bias[tx*8 + 2*j]);

#pragma unroll
    for (int i = 0; i < 8; i++) {
        int row = row0 + ty*8 + i;
        if (row >= M) continue;
        float* orow = out + (size_t)row*CDIM + tx*8;
        const float* xrow = (EPI == 2) ? (xold + (size_t)row*CDIM + tx*8) : nullptr;
#pragma unroll
        for (int jj = 0; jj < 2; jj++) {
            float2 p0 = unpack2(acc[i][2*jj]);
            float2 p1 = unpack2(acc[i][2*jj + 1]);
            float4 v = make_float4(p0.x + bb[2*jj].x,   p0.y + bb[2*jj].y,
                                   p1.x + bb[2*jj+1].x, p1.y + bb[2*jj+1].y);
            if (EPI == 0) {
                v.x = fmaxf(v.x, 0.f); v.y = fmaxf(v.y, 0.f);
                v.z = fmaxf(v.z, 0.f); v.w = fmaxf(v.w, 0.f);
            }
            if (EPI == 2) {
                float4 xo = *reinterpret_cast<const float4*>(xrow + 4*jj);
                v.x = g*v.x + og*xo.x; v.y = g*v.y + og*xo.y;
                v.z = g*v.z + og*xo.z; v.w = g*v.w + og*xo.w;
            }
            *reinterpret_cast<float4*>(orow + 4*jj) = v;
        }
    }
}

// ---------------- small kernels ----------------
__global__ void fill_k(float* p, float val, int n) {
    int i = blockIdx.x*blockDim.x + threadIdx.x;
    if (i < n) p[i] = val;
}

// embedding gather + mean + relu (fp32 out)
__global__ void pool_k(const int* __restrict__ tok, const float* __restrict__ emb,
                       float* __restrict__ out, int N) {
    int node = blockIdx.x*2 + (threadIdx.x >> 7);
    int c = threadIdx.x & 127;
    if (node >= N) return;
    const int* tp = tok + (size_t)node*NTOK;
    float s = 0.f;
#pragma unroll
    for (int t = 0; t < NTOK; t++) s += emb[(size_t)tp[t]*CDIM + c];
    s *= (1.0f/NTOK);
    out[(size_t)node*CDIM + c] = s > 0.f ? s : 0.f;
}

#define NPB 32   // nodes per block in qr_k / aggprep_k

// qr[n, h, d] = (p_rel[h]*scale) * sum_e a_rel[h][d][e] * q[n, h, e]   (per relation)
__global__ void qr_k(const float* __restrict__ q, const float* __restrict__ a_rel,
                     const float* __restrict__ p_rel, float* __restrict__ qr, int l) {
    const int r = blockIdx.y;
    const int N = (r == 1) ? NFUNC : NSTMT;
    const float* qs = q + ((r == 1) ? (size_t)NSTMT*CDIM : 0);
    float* out = qr + ((r == 0) ? 0 : (r == 1) ? (size_t)NSTMT*CDIM
                                               : (size_t)(NSTMT+NFUNC)*CDIM);
    __shared__ float At[NH*HD*HD];   // transposed: At[h][e][d]
    __shared__ float ps[NH];
    const int tid = threadIdx.x;
    const float* Ag = a_rel + (size_t)(l*3 + r)*NH*HD*HD;
    for (int i = tid; i < NH*HD*HD; i += 256) {
        int h = i >> 8, d = (i >> 4) & 15, e = i & 15;
        At[(h << 8) + (e << 4) + d] = Ag[i];
    }
    if (tid < NH) ps[tid] = p_rel[(l*3 + r)*NH + tid] * 0.25f;
    __syncthreads();

    const int c = tid & 127;
    const int h = c >> 4, d = c & 15;
    const float* Ah = At + (h << 8) + d;
    const float psh = ps[h];
    int node0 = blockIdx.x * NPB + (tid >> 7);
#pragma unroll 4
    for (int ni = 0; ni < NPB/2; ni++) {
        int node = node0 + ni*2;
        if (node >= N) break;
        const float* qrow = qs + (size_t)node*CDIM + h*HD;
        float sum = 0.f;
#pragma unroll
        for (int e = 0; e < HD; e++) sum += Ah[e << 4] * __ldg(qrow + e);
        out[(size_t)node*CDIM + c] = sum * psh;
    }
}

// epilogue prep: P[n,h,e] = gelu( sum_r (1/s_r) * sum_d agg_r[n,h,d] * M_r[h][d][e] )
template<int NR>
__global__ void aggprep_k(const float* __restrict__ agg0, const float* __restrict__ agg2,
                          const float* __restrict__ s0, const float* __restrict__ s2,
                          const float* __restrict__ M0g, const float* __restrict__ M2g,
                          float* __restrict__ P, int N) {
    __shared__ float M0[NH*HD*HD];   // M[h][d][e] — e contiguous
    __shared__ float M2[NR == 2 ? NH*HD*HD : 1];
    const int tid = threadIdx.x;
    for (int i = tid; i < NH*HD*HD; i += 256) {
        M0[i] = M0g[i];
        if (NR == 2) M2[i] = M2g[i];
    }
    __syncthreads();

    const int c = tid & 127;
    const int h = c >> 4, e = c & 15;
    int node0 = blockIdx.x * NPB + (tid >> 7);
#pragma unroll 4
    for (int ni = 0; ni < NPB/2; ni++) {
        int node = node0 + ni*2;
        if (node >= N) break;
        const float* a0 = agg0 + (size_t)node*CDIM + h*HD;
        float w0 = 1.0f / (s0[(size_t)node*NH + h] + 1e-16f);
        float t0 = 0.f;
#pragma unroll
        for (int d = 0; d < HD; d++) t0 += __ldg(a0 + d) * M0[(h << 8) + (d << 4) + e];
        float vv = t0 * w0;
        if (NR == 2) {
            const float* a2 = agg2 + (size_t)node*CDIM + h*HD;
            float w2 = 1.0f / (s2[(size_t)node*NH + h] + 1e-16f);
            float t2 = 0.f;
#pragma unroll
            for (int d = 0; d < HD; d++) t2 += __ldg(a2 + d) * M2[(h << 8) + (d << 4) + e];
            vv += t2 * w2;
        }
        P[(size_t)node*CDIM + c] = gelu_f(vv);
    }
}

// ---------------- fused edge kernel (all 3 relations via blockIdx.y) ----------------
struct EdgeArgs {
    const int*   src[3];
    const int*   dst[3];
    const float* qr[3];
    const float* k[3];
    const float* v[3];
    float*       sb[3];
    float*       agg[3];
};

__global__ void edge_k(EdgeArgs ea, int ne) {
    int e = (blockIdx.x*blockDim.x + threadIdx.x) >> 5;
    int lane = threadIdx.x & 31;
    if (e >= ne) return;
    int r = blockIdx.y;
    int s = ea.src[r][e], d = ea.dst[r][e];
    float4 qv = *reinterpret_cast<const float4*>(ea.qr[r] + (size_t)d*CDIM + lane*4);
    float4 kv = *reinterpret_cast<const float4*>(ea.k[r]  + (size_t)s*CDIM + lane*4);
    float p = qv.x*kv.x + qv.y*kv.y + qv.z*kv.z + qv.w*kv.w;
    p += __shfl_xor_sync(0xffffffffu, p, 1);
    p += __shfl_xor_sync(0xffffffffu, p, 2);
    float ev = __expf(p);
    int h = lane >> 2;
    if ((lane & 3) == 0) atomicAdd(ea.sb[r] + (size_t)d*NH + h, ev);
    float4 v = *reinterpret_cast<const float4*>(ea.v[r] + (size_t)s*CDIM + lane*4);
    v.x *= ev; v.y *= ev; v.z *= ev; v.w *= ev;
    atomicAdd(reinterpret_cast<float4*>(ea.agg[r] + (size_t)d*CDIM + lane*4), v);
}

// ---------------- host launcher ----------------
static inline int GB(int m) { return (m + 127) / 128; }

extern "C" void kernel_launch(void* const* d_in, const int* in_sizes, int n_in,
                              void* d_out, int out_size) {
    const int* tok_stmt = (const int*)d_in[0];
    const int* tok_func = (const int*)d_in[1];
    const int* esrc[3] = {(const int*)d_in[2], (const int*)d_in[4], (const int*)d_in[6]};
    const int* edst[3] = {(const int*)d_in[3], (const int*)d_in[5], (const int*)d_in[7]};
    const float* emb   = (const float*)d_in[8];
    const float* lin_w = (const float*)d_in[9];
    const float* lin_b = (const float*)d_in[10];
    const float* kw = (const float*)d_in[11];
    const float* kb = (const float*)d_in[12];
    const float* qw = (const float*)d_in[13];
    const float* qb = (const float*)d_in[14];
    const float* vw = (const float*)d_in[15];
    const float* vb = (const float*)d_in[16];
    const float* aw = (const float*)d_in[17];
    const float* ab = (const float*)d_in[18];
    const float* skip  = (const float*)d_in[19];
    const float* a_rel = (const float*)d_in[20];
    const float* m_rel = (const float*)d_in[21];
    const float* p_rel = (const float*)d_in[22];
    float* x = (float*)d_out;

    float *q, *k, *v, *qr, *agg, *agg2, *sbuf, *p2;
    cudaGetSymbolAddress((void**)&q,    g_q);
    cudaGetSymbolAddress((void**)&k,    g_k);
    cudaGetSymbolAddress((void**)&v,    g_v);
    cudaGetSymbolAddress((void**)&qr,   g_qr);
    cudaGetSymbolAddress((void**)&agg,  g_agg);
    cudaGetSymbolAddress((void**)&agg2, g_agg2);
    cudaGetSymbolAddress((void**)&sbuf, g_s);
    cudaGetSymbolAddress((void**)&p2,   g_p2);

    const size_t XF = (size_t)NSTMT*CDIM;

    // ---- encoder: pool + per-type linear + relu ----
    pool_k<<<(NSTMT+1)/2, 256>>>(tok_stmt, emb, p2, NSTMT);
    pool_k<<<(NFUNC+1)/2, 256>>>(tok_func, emb, p2 + XF, NFUNC);
    {
        Slabs s{}; s.W[0] = lin_w; s.B[0] = lin_b; s.O[0] = x;
        gemm_k<0><<<dim3(GB(NSTMT),1), 256>>>(p2, s, NSTMT, nullptr, nullptr);
        Slabs f{}; f.W[0] = lin_w + CC; f.B[0] = lin_b + CDIM; f.O[0] = x + XF;
        gemm_k<0><<<dim3(GB(NFUNC),1), 256>>>(p2 + XF, f, NFUNC, nullptr, nullptr);
    }

    for (int l = 0; l < 2; l++) {
        // raw projections q/k/v for both types (slab over 3 weights)
        {
            Slabs s{};
            s.W[0] = qw + (size_t)(l*2+0)*CC; s.B[0] = qb + (size_t)(l*2+0)*CDIM; s.O[0] = q;
            s.W[1] = kw + (size_t)(l*2+0)*CC; s.B[1] = kb + (size_t)(l*2+0)*CDIM; s.O[1] = k;
            s.W[2] = vw + (size_t)(l*2+0)*CC; s.B[2] = vb + (size_t)(l*2+0)*CDIM; s.O[2] = v;
            gemm_k<1><<<dim3(GB(NSTMT),3), 256>>>(x, s, NSTMT, nullptr, nullptr);
            Slabs f{};
            f.W[0] = qw + (size_t)(l*2+1)*CC; f.B[0] = qb + (size_t)(l*2+1)*CDIM; f.O[0] = q + XF;
            f.W[1] = kw + (size_t)(l*2+1)*CC; f.B[1] = kb + (size_t)(l*2+1)*CDIM; f.O[1] = k + XF;
            f.W[2] = vw + (size_t)(l*2+1)*CC; f.B[2] = vb + (size_t)(l*2+1)*CDIM; f.O[2] = v + XF;
            gemm_k<1><<<dim3(GB(NFUNC),3), 256>>>(x + XF, f, NFUNC, nullptr, nullptr);
        }

        // qr = a_rel^T q (dst side), p_rel*scale folded
        qr_k<<<dim3((NSTMT + NPB - 1)/NPB, 3), 256>>>(q, a_rel, p_rel, qr, l);

        fill_k<<<((int)(NTOT*(size_t)CDIM) + 255)/256, 256>>>(agg, 0.f, NTOT*CDIM);
        fill_k<<<((int)(NSTMT*(size_t)CDIM) + 255)/256, 256>>>(agg2, 0.f, NSTMT*CDIM);
        fill_k<<<(3*NSTMT*NH + 255)/256, 256>>>(sbuf, 0.f, 3*NSTMT*NH);

        EdgeArgs ea;
        const float* qroff[3] = {qr, qr + XF, qr + XF + (size_t)NFUNC*CDIM};
        for (int r = 0; r < 3; r++) {
            ea.src[r] = esrc[r]; ea.dst[r] = edst[r];
            ea.qr[r] = qroff[r];
            ea.k[r] = k + ((r == 2) ? XF : 0);   // src type: stmt,stmt,func
            ea.v[r] = v + ((r == 2) ? XF : 0);
            ea.sb[r] = sbuf + (size_t)r*NSTMT*NH;
        }
        ea.agg[0] = agg;          // rel0 -> stmt
        ea.agg[1] = agg + XF;     // rel1 -> func
        ea.agg[2] = agg2;         // rel2 -> stmt
        edge_k<<<dim3((NE*32 + 255)/256, 3), 256>>>(ea, NE);

        // epilogue prep: P = gelu( sum_r m_rel_r . agg_r / s_r )
        const float* M0 = m_rel + (size_t)(l*3 + 0)*NH*HD*HD;
        const float* M1 = m_rel + (size_t)(l*3 + 1)*NH*HD*HD;
        const float* M2 = m_rel + (size_t)(l*3 + 2)*NH*HD*HD;
        aggprep_k<2><<<(NSTMT + NPB - 1)/NPB, 256>>>(agg, agg2,
            sbuf + 0*(size_t)NSTMT*NH, sbuf + 2*(size_t)NSTMT*NH, M0, M2, p2, NSTMT);
        aggprep_k<1><<<(NFUNC + NPB - 1)/NPB, 256>>>(agg + XF, nullptr,
            sbuf + 1*(size_t)NSTMT*NH, nullptr, M1, nullptr, p2 + XF, NFUNC);

        // epilogue: x = g*(P @ aw + ab) + (1-g)*x
        {
            Slabs s{}; s.W[0] = aw + (size_t)(l*2+0)*CC; s.B[0] = ab + (size_t)(l*2+0)*CDIM; s.O[0] = x;
            gemm_k<2><<<dim3(GB(NSTMT),1), 256>>>(p2, s, NSTMT, x, skip + l*2 + 0);
            Slabs f{}; f.W[0] = aw + (size_t)(l*2+1)*CC; f.B[0] = ab + (size_t)(l*2+1)*CDIM; f.O[0] = x + XF;
            gemm_k<2><<<dim3(GB(NFUNC),1), 256>>>(p2 + XF, f, NFUNC, x + XF, skip + l*2 + 1);
        }
    }
}

// round 9
// speedup vs baseline: 2.1725x; 1.0807x over previous
#include <cuda_runtime.h>
#include <math.h>

#define NSTMT 100000
#define NFUNC 50000
#define NTOT  150000
#define CDIM  128
#define NH    8
#define HD    16
#define NE    200000
#define NTOK  16
#define CC    (CDIM*CDIM)
#define NB_S  782    // ceil(NSTMT/128)
#define NB_F  391    // ceil(NFUNC/128)

typedef unsigned long long ull;

// ---------------- scratch (static device globals; no allocation) ----------------
__device__ __align__(16) float g_k[(size_t)NTOT*CDIM];                // raw k
__device__ __align__(16) float g_qr[(size_t)(2*NSTMT+NFUNC)*CDIM];    // qr0 | qr1 | qr2
__device__ __align__(16) float g_vr[(size_t)(2*NSTMT+NFUNC)*CDIM];    // vr0 | vr1 | vr2
__device__ __align__(16) float g_agg[(size_t)NTOT*CDIM];              // agg r0(stmt) + r1(func)
__device__ __align__(16) float g_agg2[(size_t)NSTMT*CDIM];            // agg r2 (stmt)
__device__ __align__(16) float g_s[(size_t)3*NSTMT*NH];               // softmax denominators
__device__ __align__(16) float g_p2[(size_t)NTOT*CDIM];               // pooled / epilogue-prep
__device__ __align__(16) float g_cw[(size_t)6*CC];                    // composed weights qr0-2,vr0-2
__device__ __align__(16) float g_cb[(size_t)6*CDIM];                  // composed biases

// ---------------- helpers ----------------
__device__ __forceinline__ float gelu_f(float x) {
    float x3 = x*x*x;
    return 0.5f*x*(1.0f + tanhf(0.7978845608028654f*(x + 0.044715f*x3)));
}
__device__ __forceinline__ void fma2(ull& c, ull a, ull b) {
    asm("fma.rn.f32x2 %0, %1, %2, %0;" : "+l"(c) : "l"(a), "l"(b));
}
__device__ __forceinline__ float2 unpack2(ull v) {
    unsigned lo, hi;
    asm("mov.b64 {%0, %1}, %2;" : "=r"(lo), "=r"(hi) : "l"(v));
    return make_float2(__uint_as_float(lo), __uint_as_float(hi));
}

// ---------------- GEMM: merged stmt+func launch, dup-A SMEM, FFMA2 core ----------------
// Block decode: first NS0*NB_S blocks are stmt tiles (NS0 slabs), rest func (NS1 slabs).
// EPI: 0 relu; 1 none; 2 blend g*v+(1-g)*xold (g from SK[slab]).
struct GArgs {
    const float* A0; const float* A1;
    const float* W[8]; const float* B[8];
    float* O[8];
    const float* SK[8]; const float* X[8];
};

template<int NS0, int NS1, int EPI>
__global__ __launch_bounds__(256) void gemm_k(GArgs ga) {
    __shared__ float Asd[16][256];   // A duplicated: Asd[k][2r]=Asd[k][2r+1]=a_r
    __shared__ float Ws[16][128];

    const int bid = blockIdx.x;
    const float* A; int M, slab, blk;
    if (NS1 == 0 || bid < NS0*NB_S) {
        slab = bid / NB_S; blk = bid - slab*NB_S; A = ga.A0; M = NSTMT;
    } else {
        int t = bid - NS0*NB_S;
        int s1 = t / NB_F; slab = NS0 + s1; blk = t - s1*NB_F; A = ga.A1; M = NFUNC;
    }
    const float* __restrict__ W = ga.W[slab];
    const float* __restrict__ bias = ga.B[slab];
    float* __restrict__ out = ga.O[slab];

    const int tid  = threadIdx.x;
    const int row0 = blk * 128;
    const int lr  = tid >> 1;
    const int lkq = (tid & 1) * 8;
    const int wk  = tid >> 4;
    const int wc  = (tid & 15) * 8;
    const int ty  = tid >> 4;
    const int tx  = tid & 15;

    const int  arow = row0 + lr;
    const bool aval = arow < M;
    const float* Ap = A + (size_t)arow * CDIM + lkq;
    const float* Wp = W + (size_t)wk * CDIM + wc;

    ull acc[8][4];
#pragma unroll
    for (int i = 0; i < 8; i++)
#pragma unroll
        for (int j = 0; j < 4; j++) acc[i][j] = 0ull;

    float4 pa0, pa1, pw0, pw1;
    const float4 z4 = make_float4(0.f, 0.f, 0.f, 0.f);

    pa0 = aval ? *reinterpret_cast<const float4*>(Ap)     : z4;
    pa1 = aval ? *reinterpret_cast<const float4*>(Ap + 4) : z4;
    pw0 = *reinterpret_cast<const float4*>(Wp);
    pw1 = *reinterpret_cast<const float4*>(Wp + 4);

#pragma unroll 1
    for (int s = 0; s < 8; s++) {
        const float* av = &pa0.x;
#pragma unroll
        for (int j = 0; j < 4; j++)
            *reinterpret_cast<float2*>(&Asd[lkq + j][2*lr]) = make_float2(av[j], av[j]);
        const float* av1 = &pa1.x;
#pragma unroll
        for (int j = 0; j < 4; j++)
            *reinterpret_cast<float2*>(&Asd[lkq + 4 + j][2*lr]) = make_float2(av1[j], av1[j]);
        *reinterpret_cast<float4*>(&Ws[wk][wc])     = pw0;
        *reinterpret_cast<float4*>(&Ws[wk][wc + 4]) = pw1;
        __syncthreads();

        if (s < 7) {
            int k0 = (s + 1) * 16;
            pa0 = aval ? *reinterpret_cast<const float4*>(Ap + k0)     : z4;
            pa1 = aval ? *reinterpret_cast<const float4*>(Ap + k0 + 4) : z4;
            pw0 = *reinterpret_cast<const float4*>(Wp + (size_t)k0 * CDIM);
            pw1 = *reinterpret_cast<const float4*>(Wp + (size_t)k0 * CDIM + 4);
        }

#pragma unroll
        for (int k = 0; k < 16; k++) {
            ull ad[8], bp[4];
#pragma unroll
            for (int t = 0; t < 4; t++)
                *reinterpret_cast<ulonglong2*>(ad + 2*t) =
                    *reinterpret_cast<const ulonglong2*>(&Asd[k][ty*16 + 4*t]);
            *reinterpret_cast<ulonglong2*>(bp)     = *reinterpret_cast<const ulonglong2*>(&Ws[k][tx*8]);
            *reinterpret_cast<ulonglong2*>(bp + 2) = *reinterpret_cast<const ulonglong2*>(&Ws[k][tx*8 + 4]);
#pragma unroll
            for (int i = 0; i < 8; i++)
#pragma unroll
                for (int j = 0; j < 4; j++) fma2(acc[i][j], ad[i], bp[j]);
        }
        if (s < 7) __syncthreads();
    }

    float g = 0.f, og = 0.f;
    const float* xold = nullptr;
    if (EPI == 2) {
        g = 1.0f/(1.0f + expf(-*ga.SK[slab])); og = 1.0f - g;
        xold = ga.X[slab];
    }
    float2 bb[4];
#pragma unroll
    for (int j = 0; j < 4; j++) bb[j] = *reinterpret_cast<const float2*>(&bias[tx*8 + 2*j]);

#pragma unroll
    for (int i = 0; i < 8; i++) {
        int row = row0 + ty*8 + i;
        if (row >= M) continue;
        float* orow = out + (size_t)row*CDIM + tx*8;
        const float* xrow = (EPI == 2) ? (xold + (size_t)row*CDIM + tx*8) : nullptr;
#pragma unroll
        for (int jj = 0; jj < 2; jj++) {
            float2 p0 = unpack2(acc[i][2*jj]);
            float2 p1 = unpack2(acc[i][2*jj + 1]);
            float4 v = make_float4(p0.x + bb[2*jj].x,   p0.y + bb[2*jj].y,
                                   p1.x + bb[2*jj+1].x, p1.y + bb[2*jj+1].y);
            if (EPI == 0) {
                v.x = fmaxf(v.x, 0.f); v.y = fmaxf(v.y, 0.f);
                v.z = fmaxf(v.z, 0.f); v.w = fmaxf(v.w, 0.f);
            }
            if (EPI == 2) {
                float4 xo = *reinterpret_cast<const float4*>(xrow + 4*jj);
                v.x = g*v.x + og*xo.x; v.y = g*v.y + og*xo.y;
                v.z = g*v.z + og*xo.z; v.w = g*v.w + og*xo.w;
            }
            *reinterpret_cast<float4*>(orow + 4*jj) = v;
        }
    }
}

// ---------------- small kernels ----------------
__global__ void fill_k(float* p, float val, int n) {
    int i = blockIdx.x*blockDim.x + threadIdx.x;
    if (i < n) p[i] = val;
}

__global__ void pool_k(const int* __restrict__ tok, const float* __restrict__ emb,
                       float* __restrict__ out, int N) {
    int node = blockIdx.x*2 + (threadIdx.x >> 7);
    int c = threadIdx.x & 127;
    if (node >= N) return;
    const int* tp = tok + (size_t)node*NTOK;
    float s = 0.f;
#pragma unroll
    for (int t = 0; t < NTOK; t++) s += emb[(size_t)tp[t]*CDIM + c];
    s *= (1.0f/NTOK);
    out[(size_t)node*CDIM + c] = s > 0.f ? s : 0.f;
}

// compose: slots 0-2 = qr (q-side, contract over e, p*scale folded, dst-typed),
//          slots 3-5 = vr (v-side, contract over d, src-typed)
__global__ void compose_k(const float* __restrict__ qw, const float* __restrict__ qb,
                          const float* __restrict__ vw, const float* __restrict__ vb,
                          const float* __restrict__ a_rel, const float* __restrict__ m_rel,
                          const float* __restrict__ p_rel, int l) {
    int idx = blockIdx.x*blockDim.x + threadIdx.x;
    const int total = 6*129*128;
    if (idx >= total) return;
    int j = idx & 127; idx >>= 7;
    int i = idx % 129; idx /= 129;
    int m = idx;                // 0..5
    int kv = m / 3, r = m % 3;
    int h = j >> 4, x2 = j & 15;   // x2 = d (qr) or e (vr)
    float sum = 0.f;
    if (kv == 0) {
        int t = (r == 1) ? 1 : 0;   // dst type
        const float* w = (i < 128)
            ? qw + (size_t)(l*2+t)*CC + (size_t)i*CDIM + h*HD
            : qb + (size_t)(l*2+t)*CDIM + h*HD;
        const float* rel = a_rel + ((size_t)(l*3+r)*NH + h)*HD*HD + x2*HD;  // [d=x2][e]
#pragma unroll
        for (int e = 0; e < HD; e++) sum += w[e] * rel[e];
        sum *= p_rel[(l*3+r)*NH + h] * 0.25f;
    } else {
        int t = (r == 2) ? 1 : 0;   // src type
        const float* w = (i < 128)
            ? vw + (size_t)(l*2+t)*CC + (size_t)i*CDIM + h*HD
            : vb + (size_t)(l*2+t)*CDIM + h*HD;
        const float* rel = m_rel + ((size_t)(l*3+r)*NH + h)*HD*HD + x2;     // [d][e=x2]
#pragma unroll
        for (int d = 0; d < HD; d++) sum += w[d] * rel[d*HD];
    }
    if (i < 128) g_cw[(size_t)m*CC + (size_t)i*CDIM + j] = sum;
    else         g_cb[(size_t)m*CDIM + j] = sum;
}

// elementwise epilogue prep: P = gelu(agg/s0 [+ agg2/s2]) — float4 coalesced
template<int NR>
__global__ void aggnorm_k(const float* __restrict__ agg, const float* __restrict__ agg2,
                          const float* __restrict__ s0, const float* __restrict__ s2,
                          float* __restrict__ P, int n4) {
    int i4 = blockIdx.x*blockDim.x + threadIdx.x;
    if (i4 >= n4) return;
    int row = i4 >> 5, h = (i4 & 31) >> 2;
    float w0 = 1.0f / (s0[(size_t)row*NH + h] + 1e-16f);
    float4 a = reinterpret_cast<const float4*>(agg)[i4];
    float4 v = make_float4(a.x*w0, a.y*w0, a.z*w0, a.w*w0);
    if (NR == 2) {
        float w2 = 1.0f / (s2[(size_t)row*NH + h] + 1e-16f);
        float4 b = reinterpret_cast<const float4*>(agg2)[i4];
        v.x += b.x*w2; v.y += b.y*w2; v.z += b.z*w2; v.w += b.w*w2;
    }
    v.x = gelu_f(v.x); v.y = gelu_f(v.y); v.z = gelu_f(v.z); v.w = gelu_f(v.w);
    reinterpret_cast<float4*>(P)[i4] = v;
}

// ---------------- fused edge kernel (all 3 relations via blockIdx.y) ----------------
struct EdgeArgs {
    const int*   src[3];
    const int*   dst[3];
    const float* qr[3];
    const float* k[3];
    const float* v[3];
    float*       sb[3];
    float*       agg[3];
};

__global__ void edge_k(EdgeArgs ea, int ne) {
    int e = (blockIdx.x*blockDim.x + threadIdx.x) >> 5;
    int lane = threadIdx.x & 31;
    if (e >= ne) return;
    int r = blockIdx.y;
    int s = ea.src[r][e], d = ea.dst[r][e];
    float4 qv = *reinterpret_cast<const float4*>(ea.qr[r] + (size_t)d*CDIM + lane*4);
    float4 kv = *reinterpret_cast<const float4*>(ea.k[r]  + (size_t)s*CDIM + lane*4);
    float p = qv.x*kv.x + qv.y*kv.y + qv.z*kv.z + qv.w*kv.w;
    p += __shfl_xor_sync(0xffffffffu, p, 1);
    p += __shfl_xor_sync(0xffffffffu, p, 2);
    float ev = __expf(p);
    int h = lane >> 2;
    if ((lane & 3) == 0) atomicAdd(ea.sb[r] + (size_t)d*NH + h, ev);
    float4 v = *reinterpret_cast<const float4*>(ea.v[r] + (size_t)s*CDIM + lane*4);
    v.x *= ev; v.y *= ev; v.z *= ev; v.w *= ev;
    atomicAdd(reinterpret_cast<float4*>(ea.agg[r] + (size_t)d*CDIM + lane*4), v);
}

// ---------------- host launcher ----------------
extern "C" void kernel_launch(void* const* d_in, const int* in_sizes, int n_in,
                              void* d_out, int out_size) {
    const int* tok_stmt = (const int*)d_in[0];
    const int* tok_func = (const int*)d_in[1];
    const int* esrc[3] = {(const int*)d_in[2], (const int*)d_in[4], (const int*)d_in[6]};
    const int* edst[3] = {(const int*)d_in[3], (const int*)d_in[5], (const int*)d_in[7]};
    const float* emb   = (const float*)d_in[8];
    const float* lin_w = (const float*)d_in[9];
    const float* lin_b = (const float*)d_in[10];
    const float* kw = (const float*)d_in[11];
    const float* kb = (const float*)d_in[12];
    const float* qw = (const float*)d_in[13];
    const float* qb = (const float*)d_in[14];
    const float* vw = (const float*)d_in[15];
    const float* vb = (const float*)d_in[16];
    const float* aw = (const float*)d_in[17];
    const float* ab = (const float*)d_in[18];
    const float* skip  = (const float*)d_in[19];
    const float* a_rel = (const float*)d_in[20];
    const float* m_rel = (const float*)d_in[21];
    const float* p_rel = (const float*)d_in[22];
    float* x = (float*)d_out;

    float *k, *qr, *vr, *agg, *agg2, *sbuf, *p2, *cw, *cb;
    cudaGetSymbolAddress((void**)&k,    g_k);
    cudaGetSymbolAddress((void**)&qr,   g_qr);
    cudaGetSymbolAddress((void**)&vr,   g_vr);
    cudaGetSymbolAddress((void**)&agg,  g_agg);
    cudaGetSymbolAddress((void**)&agg2, g_agg2);
    cudaGetSymbolAddress((void**)&sbuf, g_s);
    cudaGetSymbolAddress((void**)&p2,   g_p2);
    cudaGetSymbolAddress((void**)&cw,   g_cw);
    cudaGetSymbolAddress((void**)&cb,   g_cb);

    const size_t XF  = (size_t)NSTMT*CDIM;
    const size_t QF2 = XF + (size_t)NFUNC*CDIM;   // qr2 offset

    // ---- encoder: pool + per-type linear + relu (one merged launch) ----
    pool_k<<<(NSTMT+1)/2, 256>>>(tok_stmt, emb, p2, NSTMT);
    pool_k<<<(NFUNC+1)/2, 256>>>(tok_func, emb, p2 + XF, NFUNC);
    {
        GArgs ga{};
        ga.A0 = p2; ga.A1 = p2 + XF;
        ga.W[0] = lin_w;      ga.B[0] = lin_b;        ga.O[0] = x;
        ga.W[1] = lin_w + CC; ga.B[1] = lin_b + CDIM; ga.O[1] = x + XF;
        gemm_k<1,1,0><<<NB_S + NB_F, 256>>>(ga);
    }

    for (int l = 0; l < 2; l++) {
        compose_k<<<(6*129*128 + 255)/256, 256>>>(qw, qb, vw, vb, a_rel, m_rel, p_rel, l);

        // one projection launch: stmt slabs [k, qr0, qr2, vr0, vr1], func slabs [k, qr1, vr2]
        {
            GArgs ga{};
            ga.A0 = x; ga.A1 = x + XF;
            ga.W[0] = kw + (size_t)(l*2+0)*CC; ga.B[0] = kb + (size_t)(l*2+0)*CDIM; ga.O[0] = k;
            ga.W[1] = cw + 0*(size_t)CC;       ga.B[1] = cb + 0*CDIM;               ga.O[1] = qr;
            ga.W[2] = cw + 2*(size_t)CC;       ga.B[2] = cb + 2*CDIM;               ga.O[2] = qr + QF2;
            ga.W[3] = cw + 3*(size_t)CC;       ga.B[3] = cb + 3*CDIM;               ga.O[3] = vr;
            ga.W[4] = cw + 4*(size_t)CC;       ga.B[4] = cb + 4*CDIM;               ga.O[4] = vr + XF;
            ga.W[5] = kw + (size_t)(l*2+1)*CC; ga.B[5] = kb + (size_t)(l*2+1)*CDIM; ga.O[5] = k + XF;
            ga.W[6] = cw + 1*(size_t)CC;       ga.B[6] = cb + 1*CDIM;               ga.O[6] = qr + XF;
            ga.W[7] = cw + 5*(size_t)CC;       ga.B[7] = cb + 5*CDIM;               ga.O[7] = vr + 2*XF;
            gemm_k<5,3,1><<<5*NB_S + 3*NB_F, 256>>>(ga);
        }

        fill_k<<<((int)(NTOT*(size_t)CDIM) + 255)/256, 256>>>(agg, 0.f, NTOT*CDIM);
        fill_k<<<((int)(NSTMT*(size_t)CDIM) + 255)/256, 256>>>(agg2, 0.f, NSTMT*CDIM);
        fill_k<<<(3*NSTMT*NH + 255)/256, 256>>>(sbuf, 0.f, 3*NSTMT*NH);

        EdgeArgs ea;
        const float* qroff[3] = {qr, qr + XF, qr + QF2};
        const float* vroff[3] = {vr, vr + XF, vr + 2*XF};
        for (int r = 0; r < 3; r++) {
            ea.src[r] = esrc[r]; ea.dst[r] = edst[r];
            ea.qr[r] = qroff[r];
            ea.k[r]  = k + ((r == 2) ? XF : 0);   // src type: stmt,stmt,func
            ea.v[r]  = vroff[r];
            ea.sb[r] = sbuf + (size_t)r*NSTMT*NH;
        }
        ea.agg[0] = agg;          // rel0 -> stmt
        ea.agg[1] = agg + XF;     // rel1 -> func
        ea.agg[2] = agg2;         // rel2 -> stmt
        edge_k<<<dim3((NE*32 + 255)/256, 3), 256>>>(ea, NE);

        // elementwise epilogue prep
        aggnorm_k<2><<<(NSTMT*32 + 255)/256, 256>>>(agg, agg2,
            sbuf + 0*(size_t)NSTMT*NH, sbuf + 2*(size_t)NSTMT*NH, p2, NSTMT*32);
        aggnorm_k<1><<<(NFUNC*32 + 255)/256, 256>>>(agg + XF, nullptr,
            sbuf + 1*(size_t)NSTMT*NH, nullptr, p2 + XF, NFUNC*32);

        // merged epilogue: x = g*(P @ aw + ab) + (1-g)*x
        {
            GArgs ga{};
            ga.A0 = p2; ga.A1 = p2 + XF;
            ga.W[0] = aw + (size_t)(l*2+0)*CC; ga.B[0] = ab + (size_t)(l*2+0)*CDIM;
            ga.O[0] = x;      ga.SK[0] = skip + l*2 + 0; ga.X[0] = x;
            ga.W[1] = aw + (size_t)(l*2+1)*CC; ga.B[1] = ab + (size_t)(l*2+1)*CDIM;
            ga.O[1] = x + XF; ga.SK[1] = skip + l*2 + 1; ga.X[1] = x + XF;
            gemm_k<1,1,2><<<NB_S + NB_F, 256>>>(ga);
        }
    }
}

// round 11
// speedup vs baseline: 2.3972x; 1.1034x over previous
#include <cuda_runtime.h>
#include <math.h>

#define NSTMT 100000
#define NFUNC 50000
#define NTOT  150000
#define CDIM  128
#define NH    8
#define HD    16
#define NE    200000
#define NTOK  16
#define CC    (CDIM*CDIM)
#define NB_S  782    // ceil(NSTMT/128)
#define NB_F  391    // ceil(NFUNC/128)

typedef unsigned long long ull;

// ---------------- scratch (static device globals; no allocation) ----------------
__device__ __align__(16) float g_q[(size_t)NTOT*CDIM];                // raw q
__device__ __align__(16) float g_k[(size_t)NTOT*CDIM];                // raw k
__device__ __align__(16) float g_v[(size_t)NTOT*CDIM];                // raw v
__device__ __align__(16) float g_qr[(size_t)(2*NSTMT+NFUNC)*CDIM];    // qr0 | qr1 | qr2
__device__ __align__(16) float g_agg[(size_t)NTOT*CDIM];              // agg r0(stmt) + r1(func)
__device__ __align__(16) float g_agg2[(size_t)NSTMT*CDIM];            // agg r2 (stmt)
__device__ __align__(16) float g_s[(size_t)3*NSTMT*NH];               // softmax denominators
__device__ __align__(16) float g_p2[(size_t)NTOT*CDIM];               // pooled / epilogue-prep

// ---------------- helpers ----------------
__device__ __forceinline__ float gelu_f(float x) {
    float x3 = x*x*x;
    return 0.5f*x*(1.0f + tanhf(0.7978845608028654f*(x + 0.044715f*x3)));
}
__device__ __forceinline__ void fma2(ull& c, ull a, ull b) {
    asm("fma.rn.f32x2 %0, %1, %2, %0;" : "+l"(c) : "l"(a), "l"(b));
}
__device__ __forceinline__ ull pack2dup(float x) {
    ull r; unsigned u = __float_as_uint(x);
    asm("mov.b64 %0, {%1, %2};" : "=l"(r) : "r"(u), "r"(u));
    return r;
}
__device__ __forceinline__ float2 unpack2(ull v) {
    unsigned lo, hi;
    asm("mov.b64 {%0, %1}, %2;" : "=r"(lo), "=r"(hi) : "l"(v));
    return make_float2(__uint_as_float(lo), __uint_as_float(hi));
}

// ---------------- GEMM: R8-proven core + merged stmt/func slab decode ----------------
// Block decode: first NS0*NB_S blocks are stmt tiles (NS0 slabs), rest func (NS1 slabs).
// EPI: 0 relu; 1 none; 2 blend g*v+(1-g)*xold (g from SK[slab]).
struct GArgs {
    const float* A0; const float* A1;
    const float* W[6]; const float* B[6];
    float* O[6];
    const float* SK[6]; const float* X[6];
};

template<int NS0, int NS1, int EPI>
__global__ __launch_bounds__(256) void gemm_k(GArgs ga) {
    __shared__ float As[16][128];
    __shared__ float Ws[16][128];

    const int bid = blockIdx.x;
    const float* A; int M, slab, blk;
    if (NS1 == 0 || bid < NS0*NB_S) {
        slab = bid / NB_S; blk = bid - slab*NB_S; A = ga.A0; M = NSTMT;
    } else {
        int t = bid - NS0*NB_S;
        int s1 = t / NB_F; slab = NS0 + s1; blk = t - s1*NB_F; A = ga.A1; M = NFUNC;
    }
    const float* __restrict__ W = ga.W[slab];
    const float* __restrict__ bias = ga.B[slab];
    float* __restrict__ out = ga.O[slab];

    const int tid  = threadIdx.x;
    const int row0 = blk * 128;
    const int lr  = tid >> 1;
    const int lkq = (tid & 1) * 8;
    const int wk  = tid >> 4;
    const int wc  = (tid & 15) * 8;
    const int ty  = tid >> 4;
    const int tx  = tid & 15;

    const int  arow = row0 + lr;
    const bool aval = arow < M;
    const float* Ap = A + (size_t)arow * CDIM + lkq;
    const float* Wp = W + (size_t)wk * CDIM + wc;

    ull acc[8][4];
#pragma unroll
    for (int i = 0; i < 8; i++)
#pragma unroll
        for (int j = 0; j < 4; j++) acc[i][j] = 0ull;

    float4 pa0, pa1, pw0, pw1;
    const float4 z4 = make_float4(0.f, 0.f, 0.f, 0.f);

    pa0 = aval ? *reinterpret_cast<const float4*>(Ap)     : z4;
    pa1 = aval ? *reinterpret_cast<const float4*>(Ap + 4) : z4;
    pw0 = *reinterpret_cast<const float4*>(Wp);
    pw1 = *reinterpret_cast<const float4*>(Wp + 4);

#pragma unroll 1
    for (int s = 0; s < 8; s++) {
        As[lkq+0][lr] = pa0.x; As[lkq+1][lr] = pa0.y; As[lkq+2][lr] = pa0.z; As[lkq+3][lr] = pa0.w;
        As[lkq+4][lr] = pa1.x; As[lkq+5][lr] = pa1.y; As[lkq+6][lr] = pa1.z; As[lkq+7][lr] = pa1.w;
        *reinterpret_cast<float4*>(&Ws[wk][wc])     = pw0;
        *reinterpret_cast<float4*>(&Ws[wk][wc + 4]) = pw1;
        __syncthreads();

        if (s < 7) {
            int k0 = (s + 1) * 16;
            pa0 = aval ? *reinterpret_cast<const float4*>(Ap + k0)     : z4;
            pa1 = aval ? *reinterpret_cast<const float4*>(Ap + k0 + 4) : z4;
            pw0 = *reinterpret_cast<const float4*>(Wp + (size_t)k0 * CDIM);
            pw1 = *reinterpret_cast<const float4*>(Wp + (size_t)k0 * CDIM + 4);
        }

#pragma unroll
        for (int k = 0; k < 16; k++) {
            float a[8]; ull bp[4];
            *reinterpret_cast<float4*>(a)     = *reinterpret_cast<const float4*>(&As[k][ty*8]);
            *reinterpret_cast<float4*>(a + 4) = *reinterpret_cast<const float4*>(&As[k][ty*8 + 4]);
            *reinterpret_cast<ulonglong2*>(bp)     = *reinterpret_cast<const ulonglong2*>(&Ws[k][tx*8]);
            *reinterpret_cast<ulonglong2*>(bp + 2) = *reinterpret_cast<const ulonglong2*>(&Ws[k][tx*8 + 4]);
#pragma unroll
            for (int i = 0; i < 8; i++) {
                ull aa = pack2dup(a[i]);
#pragma unroll
                for (int j = 0; j < 4; j++) fma2(acc[i][j], aa, bp[j]);
            }
        }
        if (s < 7) __syncthreads();
    }

    float g = 0.f, og = 0.f;
    const float* xold = nullptr;
    if (EPI == 2) {
        g = 1.0f/(1.0f + expf(-*ga.SK[slab])); og = 1.0f - g;
        xold = ga.X[slab];
    }
    float2 bb[4];
#pragma unroll
    for (int j = 0; j < 4; j++) bb[j] = *reinterpret_cast<const float2*>(&bias[tx*8 + 2*j]);

#pragma unroll
    for (int i = 0; i < 8; i++) {
        int row = row0 + ty*8 + i;
        if (row >= M) continue;
        float* orow = out + (size_t)row*CDIM + tx*8;
        const float* xrow = (EPI == 2) ? (xold + (size_t)row*CDIM + tx*8) : nullptr;
#pragma unroll
        for (int jj = 0; jj < 2; jj++) {
            float2 p0 = unpack2(acc[i][2*jj]);
            float2 p1 = unpack2(acc[i][2*jj + 1]);
            float4 v = make_float4(p0.x + bb[2*jj].x,   p0.y + bb[2*jj].y,
                                   p1.x + bb[2*jj+1].x, p1.y + bb[2*jj+1].y);
            if (EPI == 0) {
                v.x = fmaxf(v.x, 0.f); v.y = fmaxf(v.y, 0.f);
                v.z = fmaxf(v.z, 0.f); v.w = fmaxf(v.w, 0.f);
            }
            if (EPI == 2) {
                float4 xo = *reinterpret_cast<const float4*>(xrow + 4*jj);
                v.x = g*v.x + og*xo.x; v.y = g*v.y + og*xo.y;
                v.z = g*v.z + og*xo.z; v.w = g*v.w + og*xo.w;
            }
            *reinterpret_cast<float4*>(orow + 4*jj) = v;
        }
    }
}

// ---------------- small kernels ----------------
__global__ void fill_k(float* p, float val, int n) {
    int i = blockIdx.x*blockDim.x + threadIdx.x;
    if (i < n) p[i] = val;
}

__global__ void pool_k(const int* __restrict__ tok, const float* __restrict__ emb,
                       float* __restrict__ out, int N) {
    int node = blockIdx.x*2 + (threadIdx.x >> 7);
    int c = threadIdx.x & 127;
    if (node >= N) return;
    const int* tp = tok + (size_t)node*NTOK;
    float s = 0.f;
#pragma unroll
    for (int t = 0; t < NTOK; t++) s += emb[(size_t)tp[t]*CDIM + c];
    s *= (1.0f/NTOK);
    out[(size_t)node*CDIM + c] = s > 0.f ? s : 0.f;
}

// qr[n,h,d] = p_rel[h]*scale * sum_e q[n,h,e] * a_rel[h,d,e]   (dst-side fold; exact)
// 32 nodes/block staged in SMEM; per-thread a_rel coeffs in registers; broadcast reads.
__global__ __launch_bounds__(256) void qr_k(const float* __restrict__ q,
        const float* __restrict__ a_rel, const float* __restrict__ p_rel,
        float* __restrict__ qrout, int l) {
    const int r = blockIdx.y;
    const int N = (r == 1) ? NFUNC : NSTMT;
    const int node0 = blockIdx.x * 32;
    if (node0 >= N) return;
    const float* qg = q + ((r == 1) ? (size_t)NSTMT*CDIM : 0);
    float* out;
    if (r == 0)      out = qrout;
    else if (r == 1) out = qrout + (size_t)NSTMT*CDIM;
    else             out = qrout + (size_t)NSTMT*CDIM + (size_t)NFUNC*CDIM;

    __shared__ float qs[32][128];
    const int tid = threadIdx.x;
    for (int i = tid; i < 1024; i += 256) {          // 32 rows x 32 float4
        int row = i >> 5, c4 = i & 31;
        float4 vv = make_float4(0.f,0.f,0.f,0.f);
        if (node0 + row < N)
            vv = reinterpret_cast<const float4*>(qg + (size_t)(node0+row)*CDIM)[c4];
        reinterpret_cast<float4*>(&qs[row][0])[c4] = vv;
    }
    const int c = tid & 127, h = c >> 4, d = c & 15;
    const float* Ab = a_rel + (((size_t)(l*3 + r)*NH + h)*HD + d)*HD;   // [e] contiguous
    float4 a0 = reinterpret_cast<const float4*>(Ab)[0];
    float4 a1 = reinterpret_cast<const float4*>(Ab)[1];
    float4 a2 = reinterpret_cast<const float4*>(Ab)[2];
    float4 a3 = reinterpret_cast<const float4*>(Ab)[3];
    const float ps = p_rel[(l*3 + r)*NH + h] * 0.25f;
    __syncthreads();

    const int half = tid >> 7;
#pragma unroll 4
    for (int ni = 0; ni < 16; ni++) {
        int node = node0 + half*16 + ni;
        if (node >= N) break;
        const float4* q4 = reinterpret_cast<const float4*>(&qs[half*16 + ni][h*HD]);
        float4 q0 = q4[0], q1 = q4[1], q2 = q4[2], q3 = q4[3];
        float s = a0.x*q0.x + a0.y*q0.y + a0.z*q0.z + a0.w*q0.w
                + a1.x*q1.x + a1.y*q1.y + a1.z*q1.z + a1.w*q1.w
                + a2.x*q2.x + a2.y*q2.y + a2.z*q2.z + a2.w*q2.w
                + a3.x*q3.x + a3.y*q3.y + a3.z*q3.z + a3.w*q3.w;
        out[(size_t)node*CDIM + c] = s * ps;
    }
}

// epilogue prep: P[n,h,e] = gelu( sum_d agg0[n,h,d]*M0[h,d,e]/s0 [+ agg2.../s2] )
template<int NR>
__global__ __launch_bounds__(256) void aggprep_k(const float* __restrict__ agg0,
        const float* __restrict__ agg2, const float* __restrict__ s0,
        const float* __restrict__ s2, const float* __restrict__ M0g,
        const float* __restrict__ M2g, float* __restrict__ P, int N) {
    __shared__ float as0[32][128];
    __shared__ float as2[NR == 2 ? 32 : 1][NR == 2 ? 128 : 4];
    const int node0 = blockIdx.x * 32;
    if (node0 >= N) return;
    const int tid = threadIdx.x;
    for (int i = tid; i < 1024; i += 256) {
        int row = i >> 5, c4 = i & 31;
        bool pr = node0 + row < N;
        float4 z = make_float4(0.f,0.f,0.f,0.f);
        reinterpret_cast<float4*>(&as0[row][0])[c4] =
            pr ? reinterpret_cast<const float4*>(agg0 + (size_t)(node0+row)*CDIM)[c4] : z;
        if (NR == 2)
            reinterpret_cast<float4*>(&as2[row][0])[c4] =
                pr ? reinterpret_cast<const float4*>(agg2 + (size_t)(node0+row)*CDIM)[c4] : z;
    }
    const int c = tid & 127, h = c >> 4, e = c & 15;
    float m0[16], m2[16];
#pragma unroll
    for (int d = 0; d < 16; d++) {
        m0[d] = M0g[((size_t)h*HD + d)*HD + e];
        if (NR == 2) m2[d] = M2g[((size_t)h*HD + d)*HD + e];
    }
    __syncthreads();

    const int half = tid >> 7;
#pragma unroll 2
    for (int ni = 0; ni < 16; ni++) {
        int node = node0 + half*16 + ni;
        if (node >= N) break;
        float w0 = 1.0f / (s0[(size_t)node*NH + h] + 1e-16f);
        const float* ar = &as0[half*16 + ni][h*HD];
        float t0 = 0.f;
#pragma unroll
        for (int d = 0; d < 16; d++) t0 += ar[d]*m0[d];
        float v = t0 * w0;
        if (NR == 2) {
            float w2 = 1.0f / (s2[(size_t)node*NH + h] + 1e-16f);
            const float* ar2 = &as2[half*16 + ni][h*HD];
            float t2 = 0.f;
#pragma unroll
            for (int d = 0; d < 16; d++) t2 += ar2[d]*m2[d];
            v += t2 * w2;
        }
        P[(size_t)node*CDIM + c] = gelu_f(v);
    }
}

// ---------------- fused edge kernel (all 3 relations via blockIdx.y) ----------------
struct EdgeArgs {
    const int*   src[3];
    const int*   dst[3];
    const float* qr[3];
    const float* k[3];
    const float* v[3];
    float*       sb[3];
    float*       agg[3];
};

__global__ void edge_k(EdgeArgs ea, int ne) {
    int e = (blockIdx.x*blockDim.x + threadIdx.x) >> 5;
    int lane = threadIdx.x & 31;
    if (e >= ne) return;
    int r = blockIdx.y;
    int s = ea.src[r][e], d = ea.dst[r][e];
    float4 qv = *reinterpret_cast<const float4*>(ea.qr[r] + (size_t)d*CDIM + lane*4);
    float4 kv = *reinterpret_cast<const float4*>(ea.k[r]  + (size_t)s*CDIM + lane*4);
    float p = qv.x*kv.x + qv.y*kv.y + qv.z*kv.z + qv.w*kv.w;
    p += __shfl_xor_sync(0xffffffffu, p, 1);
    p += __shfl_xor_sync(0xffffffffu, p, 2);
    float ev = __expf(p);
    int h = lane >> 2;
    if ((lane & 3) == 0) atomicAdd(ea.sb[r] + (size_t)d*NH + h, ev);
    float4 v = *reinterpret_cast<const float4*>(ea.v[r] + (size_t)s*CDIM + lane*4);
    v.x *= ev; v.y *= ev; v.z *= ev; v.w *= ev;
    atomicAdd(reinterpret_cast<float4*>(ea.agg[r] + (size_t)d*CDIM + lane*4), v);
}

// ---------------- host launcher ----------------
extern "C" void kernel_launch(void* const* d_in, const int* in_sizes, int n_in,
                              void* d_out, int out_size) {
    const int* tok_stmt = (const int*)d_in[0];
    const int* tok_func = (const int*)d_in[1];
    const int* esrc[3] = {(const int*)d_in[2], (const int*)d_in[4], (const int*)d_in[6]};
    const int* edst[3] = {(const int*)d_in[3], (const int*)d_in[5], (const int*)d_in[7]};
    const float* emb   = (const float*)d_in[8];
    const float* lin_w = (const float*)d_in[9];
    const float* lin_b = (const float*)d_in[10];
    const float* kw = (const float*)d_in[11];
    const float* kb = (const float*)d_in[12];
    const float* qw = (const float*)d_in[13];
    const float* qb = (const float*)d_in[14];
    const float* vw = (const float*)d_in[15];
    const float* vb = (const float*)d_in[16];
    const float* aw = (const float*)d_in[17];
    const float* ab = (const float*)d_in[18];
    const float* skip  = (const float*)d_in[19];
    const float* a_rel = (const float*)d_in[20];
    const float* m_rel = (const float*)d_in[21];
    const float* p_rel = (const float*)d_in[22];
    float* x = (float*)d_out;

    float *q, *k, *v, *qr, *agg, *agg2, *sbuf, *p2;
    cudaGetSymbolAddress((void**)&q,    g_q);
    cudaGetSymbolAddress((void**)&k,    g_k);
    cudaGetSymbolAddress((void**)&v,    g_v);
    cudaGetSymbolAddress((void**)&qr,   g_qr);
    cudaGetSymbolAddress((void**)&agg,  g_agg);
    cudaGetSymbolAddress((void**)&agg2, g_agg2);
    cudaGetSymbolAddress((void**)&sbuf, g_s);
    cudaGetSymbolAddress((void**)&p2,   g_p2);

    const size_t XF  = (size_t)NSTMT*CDIM;
    const size_t QF2 = XF + (size_t)NFUNC*CDIM;   // qr2 offset

    // ---- encoder: pool + per-type linear + relu (merged) ----
    pool_k<<<(NSTMT+1)/2, 256>>>(tok_stmt, emb, p2, NSTMT);
    pool_k<<<(NFUNC+1)/2, 256>>>(tok_func, emb, p2 + XF, NFUNC);
    {
        GArgs ga{};
        ga.A0 = p2; ga.A1 = p2 + XF;
        ga.W[0] = lin_w;      ga.B[0] = lin_b;        ga.O[0] = x;
        ga.W[1] = lin_w + CC; ga.B[1] = lin_b + CDIM; ga.O[1] = x + XF;
        gemm_k<1,1,0><<<NB_S + NB_F, 256>>>(ga);
    }

    for (int l = 0; l < 2; l++) {
        // raw projections: one merged launch, stmt slabs [q,k,v], func slabs [q,k,v]
        {
            GArgs ga{};
            ga.A0 = x; ga.A1 = x + XF;
            ga.W[0] = qw + (size_t)(l*2+0)*CC; ga.B[0] = qb + (size_t)(l*2+0)*CDIM; ga.O[0] = q;
            ga.W[1] = kw + (size_t)(l*2+0)*CC; ga.B[1] = kb + (size_t)(l*2+0)*CDIM; ga.O[1] = k;
            ga.W[2] = vw + (size_t)(l*2+0)*CC; ga.B[2] = vb + (size_t)(l*2+0)*CDIM; ga.O[2] = v;
            ga.W[3] = qw + (size_t)(l*2+1)*CC; ga.B[3] = qb + (size_t)(l*2+1)*CDIM; ga.O[3] = q + XF;
            ga.W[4] = kw + (size_t)(l*2+1)*CC; ga.B[4] = kb + (size_t)(l*2+1)*CDIM; ga.O[4] = k + XF;
            ga.W[5] = vw + (size_t)(l*2+1)*CC; ga.B[5] = vb + (size_t)(l*2+1)*CDIM; ga.O[5] = v + XF;
            gemm_k<3,3,1><<<3*NB_S + 3*NB_F, 256>>>(ga);
        }

        // qr = dst-side a_rel fold (3 relations in one launch)
        qr_k<<<dim3((NSTMT + 31)/32, 3), 256>>>(q, a_rel, p_rel, qr, l);

        fill_k<<<((int)(NTOT*(size_t)CDIM) + 255)/256, 256>>>(agg, 0.f, NTOT*CDIM);
        fill_k<<<((int)(NSTMT*(size_t)CDIM) + 255)/256, 256>>>(agg2, 0.f, NSTMT*CDIM);
        fill_k<<<(3*NSTMT*NH + 255)/256, 256>>>(sbuf, 0.f, 3*NSTMT*NH);

        EdgeArgs ea;
        const float* qroff[3] = {qr, qr + XF, qr + QF2};
        for (int r = 0; r < 3; r++) {
            ea.src[r] = esrc[r]; ea.dst[r] = edst[r];
            ea.qr[r] = qroff[r];
            ea.k[r]  = k + ((r == 2) ? XF : 0);   // src type: stmt,stmt,func
            ea.v[r]  = v + ((r == 2) ? XF : 0);
            ea.sb[r] = sbuf + (size_t)r*NSTMT*NH;
        }
        ea.agg[0] = agg;          // rel0 -> stmt
        ea.agg[1] = agg + XF;     // rel1 -> func
        ea.agg[2] = agg2;         // rel2 -> stmt
        edge_k<<<dim3((NE*32 + 255)/256, 3), 256>>>(ea, NE);

        // epilogue prep: P = gelu( m_rel-transform + normalize )
        const float* M0 = m_rel + (size_t)(l*3 + 0)*NH*HD*HD;
        const float* M1 = m_rel + (size_t)(l*3 + 1)*NH*HD*HD;
        const float* M2 = m_rel + (size_t)(l*3 + 2)*NH*HD*HD;
        aggprep_k<2><<<(NSTMT + 31)/32, 256>>>(agg, agg2,
            sbuf + 0*(size_t)NSTMT*NH, sbuf + 2*(size_t)NSTMT*NH, M0, M2, p2, NSTMT);
        aggprep_k<1><<<(NFUNC + 31)/32, 256>>>(agg + XF, nullptr,
            sbuf + 1*(size_t)NSTMT*NH, nullptr, M1, nullptr, p2 + XF, NFUNC);

        // merged epilogue: x = g*(P @ aw + ab) + (1-g)*x
        {
            GArgs ga{};
            ga.A0 = p2; ga.A1 = p2 + XF;
            ga.W[0] = aw + (size_t)(l*2+0)*CC; ga.B[0] = ab + (size_t)(l*2+0)*CDIM;
            ga.O[0] = x;      ga.SK[0] = skip + l*2 + 0; ga.X[0] = x;
            ga.W[1] = aw + (size_t)(l*2+1)*CC; ga.B[1] = ab + (size_t)(l*2+1)*CDIM;
            ga.O[1] = x + XF; ga.SK[1] = skip + l*2 + 1; ga.X[1] = x + XF;
            gemm_k<1,1,2><<<NB_S + NB_F, 256>>>(ga);
        }
    }
}

// round 12
// speedup vs baseline: 2.5270x; 1.0542x over previous
#include <cuda_runtime.h>
#include <cuda_fp16.h>
#include <math.h>

#define NSTMT 100000
#define NFUNC 50000
#define NTOT  150000
#define CDIM  128
#define NH    8
#define HD    16
#define NE    200000
#define NTOK  16
#define CC    (CDIM*CDIM)
#define NB_S  782    // ceil(NSTMT/128)
#define NB_F  391    // ceil(NFUNC/128)

typedef unsigned long long ull;

// ---------------- scratch (static device globals; no allocation) ----------------
__device__ __align__(16) float  g_q[(size_t)NTOT*CDIM];                // raw q (fp32)
__device__ __align__(16) __half g_k16[(size_t)NTOT*CDIM];              // k (fp16)
__device__ __align__(16) __half g_v16[(size_t)NTOT*CDIM];              // v (fp16)
__device__ __align__(16) __half g_qr16[(size_t)(2*NSTMT+NFUNC)*CDIM];  // qr0|qr1|qr2 (fp16)
__device__ __align__(16) float  g_agg[(size_t)NTOT*CDIM];              // agg r0(stmt)+r1(func)
__device__ __align__(16) float  g_agg2[(size_t)NSTMT*CDIM];            // agg r2 (stmt)
__device__ __align__(16) float  g_s[(size_t)3*NSTMT*NH];               // softmax denominators
__device__ __align__(16) float  g_p2[(size_t)NTOT*CDIM];               // pooled / epilogue-prep

// ---------------- helpers ----------------
__device__ __forceinline__ float gelu_f(float x) {
    float x3 = x*x*x;
    return 0.5f*x*(1.0f + tanhf(0.7978845608028654f*(x + 0.044715f*x3)));
}
__device__ __forceinline__ void fma2(ull& c, ull a, ull b) {
    asm("fma.rn.f32x2 %0, %1, %2, %0;" : "+l"(c) : "l"(a), "l"(b));
}
__device__ __forceinline__ ull pack2dup(float x) {
    ull r; unsigned u = __float_as_uint(x);
    asm("mov.b64 %0, {%1, %2};" : "=l"(r) : "r"(u), "r"(u));
    return r;
}
__device__ __forceinline__ float2 unpack2(ull v) {
    unsigned lo, hi;
    asm("mov.b64 {%0, %1}, %2;" : "=r"(lo), "=r"(hi) : "l"(v));
    return make_float2(__uint_as_float(lo), __uint_as_float(hi));
}

// ---------------- GEMM: R8-proven core + merged stmt/func slab decode ----------------
// Block decode: first NS0*NB_S blocks are stmt tiles (NS0 slabs), rest func (NS1 slabs).
// EPI: 0 relu; 1 none; 2 blend. HF[slab]: store fp16 (EPI==1 path only).
struct GArgs {
    const float* A0; const float* A1;
    const float* W[6]; const float* B[6];
    float* O[6];
    const float* SK[6]; const float* X[6];
    int HF[6];
};

template<int NS0, int NS1, int EPI>
__global__ __launch_bounds__(256) void gemm_k(GArgs ga) {
    __shared__ float As[16][128];
    __shared__ float Ws[16][128];

    const int bid = blockIdx.x;
    const float* A; int M, slab, blk;
    if (NS1 == 0 || bid < NS0*NB_S) {
        slab = bid / NB_S; blk = bid - slab*NB_S; A = ga.A0; M = NSTMT;
    } else {
        int t = bid - NS0*NB_S;
        int s1 = t / NB_F; slab = NS0 + s1; blk = t - s1*NB_F; A = ga.A1; M = NFUNC;
    }
    const float* __restrict__ W = ga.W[slab];
    const float* __restrict__ bias = ga.B[slab];
    float* __restrict__ out = ga.O[slab];

    const int tid  = threadIdx.x;
    const int row0 = blk * 128;
    const int lr  = tid >> 1;
    const int lkq = (tid & 1) * 8;
    const int wk  = tid >> 4;
    const int wc  = (tid & 15) * 8;
    const int ty  = tid >> 4;
    const int tx  = tid & 15;

    const int  arow = row0 + lr;
    const bool aval = arow < M;
    const float* Ap = A + (size_t)arow * CDIM + lkq;
    const float* Wp = W + (size_t)wk * CDIM + wc;

    ull acc[8][4];
#pragma unroll
    for (int i = 0; i < 8; i++)
#pragma unroll
        for (int j = 0; j < 4; j++) acc[i][j] = 0ull;

    float4 pa0, pa1, pw0, pw1;
    const float4 z4 = make_float4(0.f, 0.f, 0.f, 0.f);

    pa0 = aval ? *reinterpret_cast<const float4*>(Ap)     : z4;
    pa1 = aval ? *reinterpret_cast<const float4*>(Ap + 4) : z4;
    pw0 = *reinterpret_cast<const float4*>(Wp);
    pw1 = *reinterpret_cast<const float4*>(Wp + 4);

#pragma unroll 1
    for (int s = 0; s < 8; s++) {
        As[lkq+0][lr] = pa0.x; As[lkq+1][lr] = pa0.y; As[lkq+2][lr] = pa0.z; As[lkq+3][lr] = pa0.w;
        As[lkq+4][lr] = pa1.x; As[lkq+5][lr] = pa1.y; As[lkq+6][lr] = pa1.z; As[lkq+7][lr] = pa1.w;
        *reinterpret_cast<float4*>(&Ws[wk][wc])     = pw0;
        *reinterpret_cast<float4*>(&Ws[wk][wc + 4]) = pw1;
        __syncthreads();

        if (s < 7) {
            int k0 = (s + 1) * 16;
            pa0 = aval ? *reinterpret_cast<const float4*>(Ap + k0)     : z4;
            pa1 = aval ? *reinterpret_cast<const float4*>(Ap + k0 + 4) : z4;
            pw0 = *reinterpret_cast<const float4*>(Wp + (size_t)k0 * CDIM);
            pw1 = *reinterpret_cast<const float4*>(Wp + (size_t)k0 * CDIM + 4);
        }

#pragma unroll
        for (int k = 0; k < 16; k++) {
            float a[8]; ull bp[4];
            *reinterpret_cast<float4*>(a)     = *reinterpret_cast<const float4*>(&As[k][ty*8]);
            *reinterpret_cast<float4*>(a + 4) = *reinterpret_cast<const float4*>(&As[k][ty*8 + 4]);
            *reinterpret_cast<ulonglong2*>(bp)     = *reinterpret_cast<const ulonglong2*>(&Ws[k][tx*8]);
            *reinterpret_cast<ulonglong2*>(bp + 2) = *reinterpret_cast<const ulonglong2*>(&Ws[k][tx*8 + 4]);
#pragma unroll
            for (int i = 0; i < 8; i++) {
                ull aa = pack2dup(a[i]);
#pragma unroll
                for (int j = 0; j < 4; j++) fma2(acc[i][j], aa, bp[j]);
            }
        }
        if (s < 7) __syncthreads();
    }

    float g = 0.f, og = 0.f;
    const float* xold = nullptr;
    if (EPI == 2) {
        g = 1.0f/(1.0f + expf(-*ga.SK[slab])); og = 1.0f - g;
        xold = ga.X[slab];
    }
    const int hf = (EPI == 1) ? ga.HF[slab] : 0;
    float2 bb[4];
#pragma unroll
    for (int j = 0; j < 4; j++) bb[j] = *reinterpret_cast<const float2*>(&bias[tx*8 + 2*j]);

#pragma unroll
    for (int i = 0; i < 8; i++) {
        int row = row0 + ty*8 + i;
        if (row >= M) continue;
        float* orow = out + (size_t)row*CDIM + tx*8;
        __half* orow16 = reinterpret_cast<__half*>(out) + (size_t)row*CDIM + tx*8;
        const float* xrow = (EPI == 2) ? (xold + (size_t)row*CDIM + tx*8) : nullptr;
#pragma unroll
        for (int jj = 0; jj < 2; jj++) {
            float2 p0 = unpack2(acc[i][2*jj]);
            float2 p1 = unpack2(acc[i][2*jj + 1]);
            float4 v = make_float4(p0.x + bb[2*jj].x,   p0.y + bb[2*jj].y,
                                   p1.x + bb[2*jj+1].x, p1.y + bb[2*jj+1].y);
            if (EPI == 0) {
                v.x = fmaxf(v.x, 0.f); v.y = fmaxf(v.y, 0.f);
                v.z = fmaxf(v.z, 0.f); v.w = fmaxf(v.w, 0.f);
            }
            if (EPI == 2) {
                float4 xo = *reinterpret_cast<const float4*>(xrow + 4*jj);
                v.x = g*v.x + og*xo.x; v.y = g*v.y + og*xo.y;
                v.z = g*v.z + og*xo.z; v.w = g*v.w + og*xo.w;
            }
            if (EPI == 1 && hf) {
                __half2 h0 = __floats2half2_rn(v.x, v.y);
                __half2 h1 = __floats2half2_rn(v.z, v.w);
                uint2 u;
                u.x = *reinterpret_cast<unsigned*>(&h0);
                u.y = *reinterpret_cast<unsigned*>(&h1);
                *reinterpret_cast<uint2*>(orow16 + 4*jj) = u;
            } else {
                *reinterpret_cast<float4*>(orow + 4*jj) = v;
            }
        }
    }
}

// ---------------- small kernels ----------------
__global__ void fill_k(float* p, float val, int n) {
    int i = blockIdx.x*blockDim.x + threadIdx.x;
    if (i < n) p[i] = val;
}

__global__ void pool_k(const int* __restrict__ tok, const float* __restrict__ emb,
                       float* __restrict__ out, int N) {
    int node = blockIdx.x*2 + (threadIdx.x >> 7);
    int c = threadIdx.x & 127;
    if (node >= N) return;
    const int* tp = tok + (size_t)node*NTOK;
    float s = 0.f;
#pragma unroll
    for (int t = 0; t < NTOK; t++) s += emb[(size_t)tp[t]*CDIM + c];
    s *= (1.0f/NTOK);
    out[(size_t)node*CDIM + c] = s > 0.f ? s : 0.f;
}

// qr[n,h,d] = p_rel[h]*scale * sum_e q[n,h,e] * a_rel[h,d,e]  -> fp16 out
__global__ __launch_bounds__(256) void qr_k(const float* __restrict__ q,
        const float* __restrict__ a_rel, const float* __restrict__ p_rel,
        __half* __restrict__ qrout, int l) {
    const int r = blockIdx.y;
    const int N = (r == 1) ? NFUNC : NSTMT;
    const int node0 = blockIdx.x * 32;
    if (node0 >= N) return;
    const float* qg = q + ((r == 1) ? (size_t)NSTMT*CDIM : 0);
    __half* out;
    if (r == 0)      out = qrout;
    else if (r == 1) out = qrout + (size_t)NSTMT*CDIM;
    else             out = qrout + (size_t)NSTMT*CDIM + (size_t)NFUNC*CDIM;

    __shared__ float qs[32][128];
    const int tid = threadIdx.x;
    for (int i = tid; i < 1024; i += 256) {
        int row = i >> 5, c4 = i & 31;
        float4 vv = make_float4(0.f,0.f,0.f,0.f);
        if (node0 + row < N)
            vv = reinterpret_cast<const float4*>(qg + (size_t)(node0+row)*CDIM)[c4];
        reinterpret_cast<float4*>(&qs[row][0])[c4] = vv;
    }
    const int c = tid & 127, h = c >> 4, d = c & 15;
    const float* Ab = a_rel + (((size_t)(l*3 + r)*NH + h)*HD + d)*HD;
    float4 a0 = reinterpret_cast<const float4*>(Ab)[0];
    float4 a1 = reinterpret_cast<const float4*>(Ab)[1];
    float4 a2 = reinterpret_cast<const float4*>(Ab)[2];
    float4 a3 = reinterpret_cast<const float4*>(Ab)[3];
    const float ps = p_rel[(l*3 + r)*NH + h] * 0.25f;
    __syncthreads();

    const int half_ = tid >> 7;
#pragma unroll 4
    for (int ni = 0; ni < 16; ni++) {
        int node = node0 + half_*16 + ni;
        if (node >= N) break;
        const float4* q4 = reinterpret_cast<const float4*>(&qs[half_*16 + ni][h*HD]);
        float4 q0 = q4[0], q1 = q4[1], q2 = q4[2], q3 = q4[3];
        float s = a0.x*q0.x + a0.y*q0.y + a0.z*q0.z + a0.w*q0.w
                + a1.x*q1.x + a1.y*q1.y + a1.z*q1.z + a1.w*q1.w
                + a2.x*q2.x + a2.y*q2.y + a2.z*q2.z + a2.w*q2.w
                + a3.x*q3.x + a3.y*q3.y + a3.z*q3.z + a3.w*q3.w;
        out[(size_t)node*CDIM + c] = __float2half(s * ps);
    }
}

// epilogue prep: P[n,h,e] = gelu( sum_d agg0[n,h,d]*M0[h,d,e]/s0 [+ agg2.../s2] )
template<int NR>
__global__ __launch_bounds__(256) void aggprep_k(const float* __restrict__ agg0,
        const float* __restrict__ agg2, const float* __restrict__ s0,
        const float* __restrict__ s2, const float* __restrict__ M0g,
        const float* __restrict__ M2g, float* __restrict__ P, int N) {
    __shared__ float as0[32][128];
    __shared__ float as2[NR == 2 ? 32 : 1][NR == 2 ? 128 : 4];
    const int node0 = blockIdx.x * 32;
    if (node0 >= N) return;
    const int tid = threadIdx.x;
    for (int i = tid; i < 1024; i += 256) {
        int row = i >> 5, c4 = i & 31;
        bool pr = node0 + row < N;
        float4 z = make_float4(0.f,0.f,0.f,0.f);
        reinterpret_cast<float4*>(&as0[row][0])[c4] =
            pr ? reinterpret_cast<const float4*>(agg0 + (size_t)(node0+row)*CDIM)[c4] : z;
        if (NR == 2)
            reinterpret_cast<float4*>(&as2[row][0])[c4] =
                pr ? reinterpret_cast<const float4*>(agg2 + (size_t)(node0+row)*CDIM)[c4] : z;
    }
    const int c = tid & 127, h = c >> 4, e = c & 15;
    float m0[16], m2[16];
#pragma unroll
    for (int d = 0; d < 16; d++) {
        m0[d] = M0g[((size_t)h*HD + d)*HD + e];
        if (NR == 2) m2[d] = M2g[((size_t)h*HD + d)*HD + e];
    }
    __syncthreads();

    const int half_ = tid >> 7;
#pragma unroll 2
    for (int ni = 0; ni < 16; ni++) {
        int node = node0 + half_*16 + ni;
        if (node >= N) break;
        float w0 = 1.0f / (s0[(size_t)node*NH + h] + 1e-16f);
        const float* ar = &as0[half_*16 + ni][h*HD];
        float t0 = 0.f;
#pragma unroll
        for (int d = 0; d < 16; d++) t0 += ar[d]*m0[d];
        float v = t0 * w0;
        if (NR == 2) {
            float w2 = 1.0f / (s2[(size_t)node*NH + h] + 1e-16f);
            const float* ar2 = &as2[half_*16 + ni][h*HD];
            float t2 = 0.f;
#pragma unroll
            for (int d = 0; d < 16; d++) t2 += ar2[d]*m2[d];
            v += t2 * w2;
        }
        P[(size_t)node*CDIM + c] = gelu_f(v);
    }
}

// ---------------- fused edge kernel (fp16 gathers, fp32 math/atomics) ----------------
struct EdgeArgs {
    const int*    src[3];
    const int*    dst[3];
    const __half* qr[3];
    const __half* k[3];
    const __half* v[3];
    float*        sb[3];
    float*        agg[3];
};

__device__ __forceinline__ void h4_to_f(uint2 u, float& a, float& b, float& c, float& d) {
    __half2 h0 = *reinterpret_cast<__half2*>(&u.x);
    __half2 h1 = *reinterpret_cast<__half2*>(&u.y);
    float2 f0 = __half22float2(h0), f1 = __half22float2(h1);
    a = f0.x; b = f0.y; c = f1.x; d = f1.y;
}

__global__ void edge_k(EdgeArgs ea, int ne) {
    int e = (blockIdx.x*blockDim.x + threadIdx.x) >> 5;
    int lane = threadIdx.x & 31;
    if (e >= ne) return;
    int r = blockIdx.y;
    int s = ea.src[r][e], d = ea.dst[r][e];
    uint2 qu = *reinterpret_cast<const uint2*>(ea.qr[r] + (size_t)d*CDIM + lane*4);
    uint2 ku = *reinterpret_cast<const uint2*>(ea.k[r]  + (size_t)s*CDIM + lane*4);
    float q0,q1,q2,q3, k0,k1,k2,k3;
    h4_to_f(qu, q0,q1,q2,q3);
    h4_to_f(ku, k0,k1,k2,k3);
    float p = q0*k0 + q1*k1 + q2*k2 + q3*k3;
    p += __shfl_xor_sync(0xffffffffu, p, 1);
    p += __shfl_xor_sync(0xffffffffu, p, 2);
    float ev = __expf(p);
    int h = lane >> 2;
    if ((lane & 3) == 0) atomicAdd(ea.sb[r] + (size_t)d*NH + h, ev);
    uint2 vu = *reinterpret_cast<const uint2*>(ea.v[r] + (size_t)s*CDIM + lane*4);
    float v0,v1,v2,v3;
    h4_to_f(vu, v0,v1,v2,v3);
    float4 m = make_float4(v0*ev, v1*ev, v2*ev, v3*ev);
    atomicAdd(reinterpret_cast<float4*>(ea.agg[r] + (size_t)d*CDIM + lane*4), m);
}

// ---------------- host launcher ----------------
extern "C" void kernel_launch(void* const* d_in, const int* in_sizes, int n_in,
                              void* d_out, int out_size) {
    const int* tok_stmt = (const int*)d_in[0];
    const int* tok_func = (const int*)d_in[1];
    const int* esrc[3] = {(const int*)d_in[2], (const int*)d_in[4], (const int*)d_in[6]};
    const int* edst[3] = {(const int*)d_in[3], (const int*)d_in[5], (const int*)d_in[7]};
    const float* emb   = (const float*)d_in[8];
    const float* lin_w = (const float*)d_in[9];
    const float* lin_b = (const float*)d_in[10];
    const float* kw = (const float*)d_in[11];
    const float* kb = (const float*)d_in[12];
    const float* qw = (const float*)d_in[13];
    const float* qb = (const float*)d_in[14];
    const float* vw = (const float*)d_in[15];
    const float* vb = (const float*)d_in[16];
    const float* aw = (const float*)d_in[17];
    const float* ab = (const float*)d_in[18];
    const float* skip  = (const float*)d_in[19];
    const float* a_rel = (const float*)d_in[20];
    const float* m_rel = (const float*)d_in[21];
    const float* p_rel = (const float*)d_in[22];
    float* x = (float*)d_out;

    float *q, *agg, *agg2, *sbuf, *p2;
    __half *k16, *v16, *qr16;
    cudaGetSymbolAddress((void**)&q,    g_q);
    cudaGetSymbolAddress((void**)&k16,  g_k16);
    cudaGetSymbolAddress((void**)&v16,  g_v16);
    cudaGetSymbolAddress((void**)&qr16, g_qr16);
    cudaGetSymbolAddress((void**)&agg,  g_agg);
    cudaGetSymbolAddress((void**)&agg2, g_agg2);
    cudaGetSymbolAddress((void**)&sbuf, g_s);
    cudaGetSymbolAddress((void**)&p2,   g_p2);

    const size_t XF  = (size_t)NSTMT*CDIM;
    const size_t QF2 = XF + (size_t)NFUNC*CDIM;

    // ---- encoder: pool + per-type linear + relu (merged) ----
    pool_k<<<(NSTMT+1)/2, 256>>>(tok_stmt, emb, p2, NSTMT);
    pool_k<<<(NFUNC+1)/2, 256>>>(tok_func, emb, p2 + XF, NFUNC);
    {
        GArgs ga{};
        ga.A0 = p2; ga.A1 = p2 + XF;
        ga.W[0] = lin_w;      ga.B[0] = lin_b;        ga.O[0] = x;
        ga.W[1] = lin_w + CC; ga.B[1] = lin_b + CDIM; ga.O[1] = x + XF;
        gemm_k<1,1,0><<<NB_S + NB_F, 256>>>(ga);
    }

    for (int l = 0; l < 2; l++) {
        // raw projections, merged: stmt [q,k16,v16], func [q,k16,v16]
        {
            GArgs ga{};
            ga.A0 = x; ga.A1 = x + XF;
            ga.W[0] = qw + (size_t)(l*2+0)*CC; ga.B[0] = qb + (size_t)(l*2+0)*CDIM;
            ga.O[0] = q;                        ga.HF[0] = 0;
            ga.W[1] = kw + (size_t)(l*2+0)*CC; ga.B[1] = kb + (size_t)(l*2+0)*CDIM;
            ga.O[1] = (float*)k16;              ga.HF[1] = 1;
            ga.W[2] = vw + (size_t)(l*2+0)*CC; ga.B[2] = vb + (size_t)(l*2+0)*CDIM;
            ga.O[2] = (float*)v16;              ga.HF[2] = 1;
            ga.W[3] = qw + (size_t)(l*2+1)*CC; ga.B[3] = qb + (size_t)(l*2+1)*CDIM;
            ga.O[3] = q + XF;                   ga.HF[3] = 0;
            ga.W[4] = kw + (size_t)(l*2+1)*CC; ga.B[4] = kb + (size_t)(l*2+1)*CDIM;
            ga.O[4] = (float*)(k16 + XF);       ga.HF[4] = 1;
            ga.W[5] = vw + (size_t)(l*2+1)*CC; ga.B[5] = vb + (size_t)(l*2+1)*CDIM;
            ga.O[5] = (float*)(v16 + XF);       ga.HF[5] = 1;
            gemm_k<3,3,1><<<3*NB_S + 3*NB_F, 256>>>(ga);
        }

        // qr = dst-side a_rel fold -> fp16 (3 relations in one launch)
        qr_k<<<dim3((NSTMT + 31)/32, 3), 256>>>(q, a_rel, p_rel, qr16, l);

        fill_k<<<((int)(NTOT*(size_t)CDIM) + 255)/256, 256>>>(agg, 0.f, NTOT*CDIM);
        fill_k<<<((int)(NSTMT*(size_t)CDIM) + 255)/256, 256>>>(agg2, 0.f, NSTMT*CDIM);
        fill_k<<<(3*NSTMT*NH + 255)/256, 256>>>(sbuf, 0.f, 3*NSTMT*NH);

        EdgeArgs ea;
        const __half* qroff[3] = {qr16, qr16 + XF, qr16 + QF2};
        for (int r = 0; r < 3; r++) {
            ea.src[r] = esrc[r]; ea.dst[r] = edst[r];
            ea.qr[r] = qroff[r];
            ea.k[r]  = k16 + ((r == 2) ? XF : 0);   // src type: stmt,stmt,func
            ea.v[r]  = v16 + ((r == 2) ? XF : 0);
            ea.sb[r] = sbuf + (size_t)r*NSTMT*NH;
        }
        ea.agg[0] = agg;          // rel0 -> stmt
        ea.agg[1] = agg + XF;     // rel1 -> func
        ea.agg[2] = agg2;         // rel2 -> stmt
        edge_k<<<dim3((NE*32 + 255)/256, 3), 256>>>(ea, NE);

        // epilogue prep: P = gelu( m_rel-transform + normalize )
        const float* M0 = m_rel + (size_t)(l*3 + 0)*NH*HD*HD;
        const float* M1 = m_rel + (size_t)(l*3 + 1)*NH*HD*HD;
        const float* M2 = m_rel + (size_t)(l*3 + 2)*NH*HD*HD;
        aggprep_k<2><<<(NSTMT + 31)/32, 256>>>(agg, agg2,
            sbuf + 0*(size_t)NSTMT*NH, sbuf + 2*(size_t)NSTMT*NH, M0, M2, p2, NSTMT);
        aggprep_k<1><<<(NFUNC + 31)/32, 256>>>(agg + XF, nullptr,
            sbuf + 1*(size_t)NSTMT*NH, nullptr, M1, nullptr, p2 + XF, NFUNC);

        // merged epilogue: x = g*(P @ aw + ab) + (1-g)*x
        {
            GArgs ga{};
            ga.A0 = p2; ga.A1 = p2 + XF;
            ga.W[0] = aw + (size_t)(l*2+0)*CC; ga.B[0] = ab + (size_t)(l*2+0)*CDIM;
            ga.O[0] = x;      ga.SK[0] = skip + l*2 + 0; ga.X[0] = x;
            ga.W[1] = aw + (size_t)(l*2+1)*CC; ga.B[1] = ab + (size_t)(l*2+1)*CDIM;
            ga.O[1] = x + XF; ga.SK[1] = skip + l*2 + 1; ga.X[1] = x + XF;
            gemm_k<1,1,2><<<NB_S + NB_F, 256>>>(ga);
        }
    }
}

// round 13
// speedup vs baseline: 2.6723x; 1.0575x over previous
#include <cuda_runtime.h>
#include <cuda_fp16.h>
#include <math.h>

#define NSTMT 100000
#define NFUNC 50000
#define NTOT  150000
#define CDIM  128
#define NH    8
#define HD    16
#define NE    200000
#define NTOK  16
#define CC    (CDIM*CDIM)
#define NB_S  782    // ceil(NSTMT/128)
#define NB_F  391    // ceil(NFUNC/128)

typedef unsigned long long ull;

// ---------------- scratch (static device globals; no allocation) ----------------
__device__ __align__(16) float  g_q[(size_t)NTOT*CDIM];                // raw q (fp32)
__device__ __align__(16) __half g_k16[(size_t)NTOT*CDIM];              // k (fp16)
__device__ __align__(16) __half g_v16[(size_t)NTOT*CDIM];              // v (fp16)
__device__ __align__(16) __half g_qr16[(size_t)(2*NSTMT+NFUNC)*CDIM];  // qr0|qr1|qr2 (fp16)
__device__ __align__(16) float  g_agg[(size_t)NTOT*CDIM];              // agg r0(stmt)+r1(func)
__device__ __align__(16) float  g_agg2[(size_t)NSTMT*CDIM];            // agg r2 (stmt)
__device__ __align__(16) float  g_s[(size_t)3*NSTMT*NH];               // softmax denominators
__device__ __align__(16) float  g_p2[(size_t)NTOT*CDIM];               // pooled / epilogue-prep

// ---------------- helpers ----------------
__device__ __forceinline__ float gelu_f(float x) {
    float x3 = x*x*x;
    return 0.5f*x*(1.0f + tanhf(0.7978845608028654f*(x + 0.044715f*x3)));
}
__device__ __forceinline__ void fma2(ull& c, ull a, ull b) {
    asm("fma.rn.f32x2 %0, %1, %2, %0;" : "+l"(c) : "l"(a), "l"(b));
}
__device__ __forceinline__ ull pack2dup(float x) {
    ull r; unsigned u = __float_as_uint(x);
    asm("mov.b64 %0, {%1, %2};" : "=l"(r) : "r"(u), "r"(u));
    return r;
}
__device__ __forceinline__ float2 unpack2(ull v) {
    unsigned lo, hi;
    asm("mov.b64 {%0, %1}, %2;" : "=r"(lo), "=r"(hi) : "l"(v));
    return make_float2(__uint_as_float(lo), __uint_as_float(hi));
}

// ---------------- GEMM: R8-proven core + merged stmt/func slab decode ----------------
struct GArgs {
    const float* A0; const float* A1;
    const float* W[6]; const float* B[6];
    float* O[6];
    const float* SK[6]; const float* X[6];
    int HF[6];
};

template<int NS0, int NS1, int EPI>
__global__ __launch_bounds__(256) void gemm_k(GArgs ga) {
    __shared__ float As[16][128];
    __shared__ float Ws[16][128];

    const int bid = blockIdx.x;
    const float* A; int M, slab, blk;
    if (NS1 == 0 || bid < NS0*NB_S) {
        slab = bid / NB_S; blk = bid - slab*NB_S; A = ga.A0; M = NSTMT;
    } else {
        int t = bid - NS0*NB_S;
        int s1 = t / NB_F; slab = NS0 + s1; blk = t - s1*NB_F; A = ga.A1; M = NFUNC;
    }
    const float* __restrict__ W = ga.W[slab];
    const float* __restrict__ bias = ga.B[slab];
    float* __restrict__ out = ga.O[slab];

    const int tid  = threadIdx.x;
    const int row0 = blk * 128;
    const int lr  = tid >> 1;
    const int lkq = (tid & 1) * 8;
    const int wk  = tid >> 4;
    const int wc  = (tid & 15) * 8;
    const int ty  = tid >> 4;
    const int tx  = tid & 15;

    const int  arow = row0 + lr;
    const bool aval = arow < M;
    const float* Ap = A + (size_t)arow * CDIM + lkq;
    const float* Wp = W + (size_t)wk * CDIM + wc;

    ull acc[8][4];
#pragma unroll
    for (int i = 0; i < 8; i++)
#pragma unroll
        for (int j = 0; j < 4; j++) acc[i][j] = 0ull;

    float4 pa0, pa1, pw0, pw1;
    const float4 z4 = make_float4(0.f, 0.f, 0.f, 0.f);

    pa0 = aval ? *reinterpret_cast<const float4*>(Ap)     : z4;
    pa1 = aval ? *reinterpret_cast<const float4*>(Ap + 4) : z4;
    pw0 = *reinterpret_cast<const float4*>(Wp);
    pw1 = *reinterpret_cast<const float4*>(Wp + 4);

#pragma unroll 1
    for (int s = 0; s < 8; s++) {
        As[lkq+0][lr] = pa0.x; As[lkq+1][lr] = pa0.y; As[lkq+2][lr] = pa0.z; As[lkq+3][lr] = pa0.w;
        As[lkq+4][lr] = pa1.x; As[lkq+5][lr] = pa1.y; As[lkq+6][lr] = pa1.z; As[lkq+7][lr] = pa1.w;
        *reinterpret_cast<float4*>(&Ws[wk][wc])     = pw0;
        *reinterpret_cast<float4*>(&Ws[wk][wc + 4]) = pw1;
        __syncthreads();

        if (s < 7) {
            int k0 = (s + 1) * 16;
            pa0 = aval ? *reinterpret_cast<const float4*>(Ap + k0)     : z4;
            pa1 = aval ? *reinterpret_cast<const float4*>(Ap + k0 + 4) : z4;
            pw0 = *reinterpret_cast<const float4*>(Wp + (size_t)k0 * CDIM);
            pw1 = *reinterpret_cast<const float4*>(Wp + (size_t)k0 * CDIM + 4);
        }

#pragma unroll
        for (int k = 0; k < 16; k++) {
            float a[8]; ull bp[4];
            *reinterpret_cast<float4*>(a)     = *reinterpret_cast<const float4*>(&As[k][ty*8]);
            *reinterpret_cast<float4*>(a + 4) = *reinterpret_cast<const float4*>(&As[k][ty*8 + 4]);
            *reinterpret_cast<ulonglong2*>(bp)     = *reinterpret_cast<const ulonglong2*>(&Ws[k][tx*8]);
            *reinterpret_cast<ulonglong2*>(bp + 2) = *reinterpret_cast<const ulonglong2*>(&Ws[k][tx*8 + 4]);
#pragma unroll
            for (int i = 0; i < 8; i++) {
                ull aa = pack2dup(a[i]);
#pragma unroll
                for (int j = 0; j < 4; j++) fma2(acc[i][j], aa, bp[j]);
            }
        }
        if (s < 7) __syncthreads();
    }

    float g = 0.f, og = 0.f;
    const float* xold = nullptr;
    if (EPI == 2) {
        g = 1.0f/(1.0f + expf(-*ga.SK[slab])); og = 1.0f - g;
        xold = ga.X[slab];
    }
    const int hf = (EPI == 1) ? ga.HF[slab] : 0;
    float2 bb[4];
#pragma unroll
    for (int j = 0; j < 4; j++) bb[j] = *reinterpret_cast<const float2*>(&bias[tx*8 + 2*j]);

#pragma unroll
    for (int i = 0; i < 8; i++) {
        int row = row0 + ty*8 + i;
        if (row >= M) continue;
        float* orow = out + (size_t)row*CDIM + tx*8;
        __half* orow16 = reinterpret_cast<__half*>(out) + (size_t)row*CDIM + tx*8;
        const float* xrow = (EPI == 2) ? (xold + (size_t)row*CDIM + tx*8) : nullptr;
#pragma unroll
        for (int jj = 0; jj < 2; jj++) {
            float2 p0 = unpack2(acc[i][2*jj]);
            float2 p1 = unpack2(acc[i][2*jj + 1]);
            float4 v = make_float4(p0.x + bb[2*jj].x,   p0.y + bb[2*jj].y,
                                   p1.x + bb[2*jj+1].x, p1.y + bb[2*jj+1].y);
            if (EPI == 0) {
                v.x = fmaxf(v.x, 0.f); v.y = fmaxf(v.y, 0.f);
                v.z = fmaxf(v.z, 0.f); v.w = fmaxf(v.w, 0.f);
            }
            if (EPI == 2) {
                float4 xo = *reinterpret_cast<const float4*>(xrow + 4*jj);
                v.x = g*v.x + og*xo.x; v.y = g*v.y + og*xo.y;
                v.z = g*v.z + og*xo.z; v.w = g*v.w + og*xo.w;
            }
            if (EPI == 1 && hf) {
                __half2 h0 = __floats2half2_rn(v.x, v.y);
                __half2 h1 = __floats2half2_rn(v.z, v.w);
                uint2 u;
                u.x = *reinterpret_cast<unsigned*>(&h0);
                u.y = *reinterpret_cast<unsigned*>(&h1);
                *reinterpret_cast<uint2*>(orow16 + 4*jj) = u;
            } else {
                *reinterpret_cast<float4*>(orow + 4*jj) = v;
            }
        }
    }
}

// ---------------- small kernels ----------------
__global__ void pool_k(const int* __restrict__ tok, const float* __restrict__ emb,
                       float* __restrict__ out, int N) {
    int node = blockIdx.x*2 + (threadIdx.x >> 7);
    int c = threadIdx.x & 127;
    if (node >= N) return;
    const int* tp = tok + (size_t)node*NTOK;
    float s = 0.f;
#pragma unroll
    for (int t = 0; t < NTOK; t++) s += emb[(size_t)tp[t]*CDIM + c];
    s *= (1.0f/NTOK);
    out[(size_t)node*CDIM + c] = s > 0.f ? s : 0.f;
}

// qr[n,h,d] = p_rel[h]*scale * sum_e q[n,h,e] * a_rel[h,d,e]  -> fp16 out
__global__ __launch_bounds__(256) void qr_k(const float* __restrict__ q,
        const float* __restrict__ a_rel, const float* __restrict__ p_rel,
        __half* __restrict__ qrout, int l) {
    const int r = blockIdx.y;
    const int N = (r == 1) ? NFUNC : NSTMT;
    const int node0 = blockIdx.x * 32;
    if (node0 >= N) return;
    const float* qg = q + ((r == 1) ? (size_t)NSTMT*CDIM : 0);
    __half* out;
    if (r == 0)      out = qrout;
    else if (r == 1) out = qrout + (size_t)NSTMT*CDIM;
    else             out = qrout + (size_t)NSTMT*CDIM + (size_t)NFUNC*CDIM;

    __shared__ float qs[32][128];
    const int tid = threadIdx.x;
    for (int i = tid; i < 1024; i += 256) {
        int row = i >> 5, c4 = i & 31;
        float4 vv = make_float4(0.f,0.f,0.f,0.f);
        if (node0 + row < N)
            vv = reinterpret_cast<const float4*>(qg + (size_t)(node0+row)*CDIM)[c4];
        reinterpret_cast<float4*>(&qs[row][0])[c4] = vv;
    }
    const int c = tid & 127, h = c >> 4, d = c & 15;
    const float* Ab = a_rel + (((size_t)(l*3 + r)*NH + h)*HD + d)*HD;
    float4 a0 = reinterpret_cast<const float4*>(Ab)[0];
    float4 a1 = reinterpret_cast<const float4*>(Ab)[1];
    float4 a2 = reinterpret_cast<const float4*>(Ab)[2];
    float4 a3 = reinterpret_cast<const float4*>(Ab)[3];
    const float ps = p_rel[(l*3 + r)*NH + h] * 0.25f;
    __syncthreads();

    const int half_ = tid >> 7;
#pragma unroll 4
    for (int ni = 0; ni < 16; ni++) {
        int node = node0 + half_*16 + ni;
        if (node >= N) break;
        const float4* q4 = reinterpret_cast<const float4*>(&qs[half_*16 + ni][h*HD]);
        float4 q0 = q4[0], q1 = q4[1], q2 = q4[2], q3 = q4[3];
        float s = a0.x*q0.x + a0.y*q0.y + a0.z*q0.z + a0.w*q0.w
                + a1.x*q1.x + a1.y*q1.y + a1.z*q1.z + a1.w*q1.w
                + a2.x*q2.x + a2.y*q2.y + a2.z*q2.z + a2.w*q2.w
                + a3.x*q3.x + a3.y*q3.y + a3.z*q3.z + a3.w*q3.w;
        out[(size_t)node*CDIM + c] = __float2half(s * ps);
    }
}

// epilogue prep: P[n,h,e] = gelu( sum_d agg0[n,h,d]*M0[h,d,e]/s0 [+ agg2.../s2] )
template<int NR>
__global__ __launch_bounds__(256) void aggprep_k(const float* __restrict__ agg0,
        const float* __restrict__ agg2, const float* __restrict__ s0,
        const float* __restrict__ s2, const float* __restrict__ M0g,
        const float* __restrict__ M2g, float* __restrict__ P, int N) {
    __shared__ float as0[32][128];
    __shared__ float as2[NR == 2 ? 32 : 1][NR == 2 ? 128 : 4];
    const int node0 = blockIdx.x * 32;
    if (node0 >= N) return;
    const int tid = threadIdx.x;
    for (int i = tid; i < 1024; i += 256) {
        int row = i >> 5, c4 = i & 31;
        bool pr = node0 + row < N;
        float4 z = make_float4(0.f,0.f,0.f,0.f);
        reinterpret_cast<float4*>(&as0[row][0])[c4] =
            pr ? reinterpret_cast<const float4*>(agg0 + (size_t)(node0+row)*CDIM)[c4] : z;
        if (NR == 2)
            reinterpret_cast<float4*>(&as2[row][0])[c4] =
                pr ? reinterpret_cast<const float4*>(agg2 + (size_t)(node0+row)*CDIM)[c4] : z;
    }
    const int c = tid & 127, h = c >> 4, e = c & 15;
    float m0[16], m2[16];
#pragma unroll
    for (int d = 0; d < 16; d++) {
        m0[d] = M0g[((size_t)h*HD + d)*HD + e];
        if (NR == 2) m2[d] = M2g[((size_t)h*HD + d)*HD + e];
    }
    __syncthreads();

    const int half_ = tid >> 7;
#pragma unroll 2
    for (int ni = 0; ni < 16; ni++) {
        int node = node0 + half_*16 + ni;
        if (node >= N) break;
        float w0 = 1.0f / (s0[(size_t)node*NH + h] + 1e-16f);
        const float* ar = &as0[half_*16 + ni][h*HD];
        float t0 = 0.f;
#pragma unroll
        for (int d = 0; d < 16; d++) t0 += ar[d]*m0[d];
        float v = t0 * w0;
        if (NR == 2) {
            float w2 = 1.0f / (s2[(size_t)node*NH + h] + 1e-16f);
            const float* ar2 = &as2[half_*16 + ni][h*HD];
            float t2 = 0.f;
#pragma unroll
            for (int d = 0; d < 16; d++) t2 += ar2[d]*m2[d];
            v += t2 * w2;
        }
        P[(size_t)node*CDIM + c] = gelu_f(v);
    }
}

// ---------------- fused edge kernel: 2 edges/warp, batched gathers ----------------
struct EdgeArgs {
    const int*    src[3];
    const int*    dst[3];
    const __half* qr[3];
    const __half* k[3];
    const __half* v[3];
    float*        sb[3];
    float*        agg[3];
};

__device__ __forceinline__ float h4dot(uint2 a, uint2 b) {
    __half2 a0 = *reinterpret_cast<__half2*>(&a.x);
    __half2 a1 = *reinterpret_cast<__half2*>(&a.y);
    __half2 b0 = *reinterpret_cast<__half2*>(&b.x);
    __half2 b1 = *reinterpret_cast<__half2*>(&b.y);
    float2 fa0 = __half22float2(a0), fa1 = __half22float2(a1);
    float2 fb0 = __half22float2(b0), fb1 = __half22float2(b1);
    return fa0.x*fb0.x + fa0.y*fb0.y + fa1.x*fb1.x + fa1.y*fb1.y;
}
__device__ __forceinline__ float4 h4scale(uint2 u, float s) {
    __half2 h0 = *reinterpret_cast<__half2*>(&u.x);
    __half2 h1 = *reinterpret_cast<__half2*>(&u.y);
    float2 f0 = __half22float2(h0), f1 = __half22float2(h1);
    return make_float4(f0.x*s, f0.y*s, f1.x*s, f1.y*s);
}

__global__ void edge_k(EdgeArgs ea, int ne2) {   // ne2 = NE/2 warps
    int w = (blockIdx.x*blockDim.x + threadIdx.x) >> 5;
    int lane = threadIdx.x & 31;
    if (w >= ne2) return;
    int r = blockIdx.y;
    int e0 = w*2, e1 = e0 + 1;
    int s0 = ea.src[r][e0], d0 = ea.dst[r][e0];
    int s1 = ea.src[r][e1], d1 = ea.dst[r][e1];
    const size_t off = (size_t)lane*4;
    // batched gather front: 6 independent loads
    uint2 qu0 = *reinterpret_cast<const uint2*>(ea.qr[r] + (size_t)d0*CDIM + off);
    uint2 ku0 = *reinterpret_cast<const uint2*>(ea.k[r]  + (size_t)s0*CDIM + off);
    uint2 qu1 = *reinterpret_cast<const uint2*>(ea.qr[r] + (size_t)d1*CDIM + off);
    uint2 ku1 = *reinterpret_cast<const uint2*>(ea.k[r]  + (size_t)s1*CDIM + off);
    uint2 vu0 = *reinterpret_cast<const uint2*>(ea.v[r]  + (size_t)s0*CDIM + off);
    uint2 vu1 = *reinterpret_cast<const uint2*>(ea.v[r]  + (size_t)s1*CDIM + off);

    float p0 = h4dot(qu0, ku0);
    float p1 = h4dot(qu1, ku1);
    p0 += __shfl_xor_sync(0xffffffffu, p0, 1);
    p1 += __shfl_xor_sync(0xffffffffu, p1, 1);
    p0 += __shfl_xor_sync(0xffffffffu, p0, 2);
    p1 += __shfl_xor_sync(0xffffffffu, p1, 2);
    float ev0 = __expf(p0);
    float ev1 = __expf(p1);
    int h = lane >> 2;
    if ((lane & 3) == 0) {
        atomicAdd(ea.sb[r] + (size_t)d0*NH + h, ev0);
        atomicAdd(ea.sb[r] + (size_t)d1*NH + h, ev1);
    }
    float4 m0 = h4scale(vu0, ev0);
    float4 m1 = h4scale(vu1, ev1);
    atomicAdd(reinterpret_cast<float4*>(ea.agg[r] + (size_t)d0*CDIM + off), m0);
    atomicAdd(reinterpret_cast<float4*>(ea.agg[r] + (size_t)d1*CDIM + off), m1);
}

// ---------------- host launcher ----------------
extern "C" void kernel_launch(void* const* d_in, const int* in_sizes, int n_in,
                              void* d_out, int out_size) {
    const int* tok_stmt = (const int*)d_in[0];
    const int* tok_func = (const int*)d_in[1];
    const int* esrc[3] = {(const int*)d_in[2], (const int*)d_in[4], (const int*)d_in[6]};
    const int* edst[3] = {(const int*)d_in[3], (const int*)d_in[5], (const int*)d_in[7]};
    const float* emb   = (const float*)d_in[8];
    const float* lin_w = (const float*)d_in[9];
    const float* lin_b = (const float*)d_in[10];
    const float* kw = (const float*)d_in[11];
    const float* kb = (const float*)d_in[12];
    const float* qw = (const float*)d_in[13];
    const float* qb = (const float*)d_in[14];
    const float* vw = (const float*)d_in[15];
    const float* vb = (const float*)d_in[16];
    const float* aw = (const float*)d_in[17];
    const float* ab = (const float*)d_in[18];
    const float* skip  = (const float*)d_in[19];
    const float* a_rel = (const float*)d_in[20];
    const float* m_rel = (const float*)d_in[21];
    const float* p_rel = (const float*)d_in[22];
    float* x = (float*)d_out;

    float *q, *agg, *agg2, *sbuf, *p2;
    __half *k16, *v16, *qr16;
    cudaGetSymbolAddress((void**)&q,    g_q);
    cudaGetSymbolAddress((void**)&k16,  g_k16);
    cudaGetSymbolAddress((void**)&v16,  g_v16);
    cudaGetSymbolAddress((void**)&qr16, g_qr16);
    cudaGetSymbolAddress((void**)&agg,  g_agg);
    cudaGetSymbolAddress((void**)&agg2, g_agg2);
    cudaGetSymbolAddress((void**)&sbuf, g_s);
    cudaGetSymbolAddress((void**)&p2,   g_p2);

    const size_t XF  = (size_t)NSTMT*CDIM;
    const size_t QF2 = XF + (size_t)NFUNC*CDIM;

    // ---- encoder: pool + per-type linear + relu (merged) ----
    pool_k<<<(NSTMT+1)/2, 256>>>(tok_stmt, emb, p2, NSTMT);
    pool_k<<<(NFUNC+1)/2, 256>>>(tok_func, emb, p2 + XF, NFUNC);
    {
        GArgs ga{};
        ga.A0 = p2; ga.A1 = p2 + XF;
        ga.W[0] = lin_w;      ga.B[0] = lin_b;        ga.O[0] = x;
        ga.W[1] = lin_w + CC; ga.B[1] = lin_b + CDIM; ga.O[1] = x + XF;
        gemm_k<1,1,0><<<NB_S + NB_F, 256>>>(ga);
    }

    for (int l = 0; l < 2; l++) {
        // raw projections, merged: stmt [q,k16,v16], func [q,k16,v16]
        {
            GArgs ga{};
            ga.A0 = x; ga.A1 = x + XF;
            ga.W[0] = qw + (size_t)(l*2+0)*CC; ga.B[0] = qb + (size_t)(l*2+0)*CDIM;
            ga.O[0] = q;                        ga.HF[0] = 0;
            ga.W[1] = kw + (size_t)(l*2+0)*CC; ga.B[1] = kb + (size_t)(l*2+0)*CDIM;
            ga.O[1] = (float*)k16;              ga.HF[1] = 1;
            ga.W[2] = vw + (size_t)(l*2+0)*CC; ga.B[2] = vb + (size_t)(l*2+0)*CDIM;
            ga.O[2] = (float*)v16;              ga.HF[2] = 1;
            ga.W[3] = qw + (size_t)(l*2+1)*CC; ga.B[3] = qb + (size_t)(l*2+1)*CDIM;
            ga.O[3] = q + XF;                   ga.HF[3] = 0;
            ga.W[4] = kw + (size_t)(l*2+1)*CC; ga.B[4] = kb + (size_t)(l*2+1)*CDIM;
            ga.O[4] = (float*)(k16 + XF);       ga.HF[4] = 1;
            ga.W[5] = vw + (size_t)(l*2+1)*CC; ga.B[5] = vb + (size_t)(l*2+1)*CDIM;
            ga.O[5] = (float*)(v16 + XF);       ga.HF[5] = 1;
            gemm_k<3,3,1><<<3*NB_S + 3*NB_F, 256>>>(ga);
        }

        // qr = dst-side a_rel fold -> fp16 (3 relations in one launch)
        qr_k<<<dim3((NSTMT + 31)/32, 3), 256>>>(q, a_rel, p_rel, qr16, l);

        // zero fills via memset nodes
        cudaMemsetAsync(agg,  0, (size_t)NTOT*CDIM*sizeof(float), 0);
        cudaMemsetAsync(agg2, 0, (size_t)NSTMT*CDIM*sizeof(float), 0);
        cudaMemsetAsync(sbuf, 0, (size_t)3*NSTMT*NH*sizeof(float), 0);

        EdgeArgs ea;
        const __half* qroff[3] = {qr16, qr16 + XF, qr16 + QF2};
        for (int r = 0; r < 3; r++) {
            ea.src[r] = esrc[r]; ea.dst[r] = edst[r];
            ea.qr[r] = qroff[r];
            ea.k[r]  = k16 + ((r == 2) ? XF : 0);   // src type: stmt,stmt,func
            ea.v[r]  = v16 + ((r == 2) ? XF : 0);
            ea.sb[r] = sbuf + (size_t)r*NSTMT*NH;
        }
        ea.agg[0] = agg;          // rel0 -> stmt
        ea.agg[1] = agg + XF;     // rel1 -> func
        ea.agg[2] = agg2;         // rel2 -> stmt
        edge_k<<<dim3((NE/2*32 + 255)/256, 3), 256>>>(ea, NE/2);

        // epilogue prep: P = gelu( m_rel-transform + normalize )
        const float* M0 = m_rel + (size_t)(l*3 + 0)*NH*HD*HD;
        const float* M1 = m_rel + (size_t)(l*3 + 1)*NH*HD*HD;
        const float* M2 = m_rel + (size_t)(l*3 + 2)*NH*HD*HD;
        aggprep_k<2><<<(NSTMT + 31)/32, 256>>>(agg, agg2,
            sbuf + 0*(size_t)NSTMT*NH, sbuf + 2*(size_t)NSTMT*NH, M0, M2, p2, NSTMT);
        aggprep_k<1><<<(NFUNC + 31)/32, 256>>>(agg + XF, nullptr,
            sbuf + 1*(size_t)NSTMT*NH, nullptr, M1, nullptr, p2 + XF, NFUNC);

        // merged epilogue: x = g*(P @ aw + ab) + (1-g)*x
        {
            GArgs ga{};
            ga.A0 = p2; ga.A1 = p2 + XF;
            ga.W[0] = aw + (size_t)(l*2+0)*CC; ga.B[0] = ab + (size_t)(l*2+0)*CDIM;
            ga.O[0] = x;      ga.SK[0] = skip + l*2 + 0; ga.X[0] = x;
            ga.W[1] = aw + (size_t)(l*2+1)*CC; ga.B[1] = ab + (size_t)(l*2+1)*CDIM;
            ga.O[1] = x + XF; ga.SK[1] = skip + l*2 + 1; ga.X[1] = x + XF;
            gemm_k<1,1,2><<<NB_S + NB_F, 256>>>(ga);
        }
    }
}

// round 16
// speedup vs baseline: 3.5589x; 1.3318x over previous
#include <cuda_runtime.h>
#include <cuda_fp16.h>
#include <math.h>

#define NSTMT 100000
#define NFUNC 50000
#define NTOT  150000
#define CDIM  128
#define NH    8
#define HD    16
#define NE    200000
#define NTOK  16
#define CC    (CDIM*CDIM)
#define NB_S  782    // ceil(NSTMT/128)
#define NB_F  391    // ceil(NFUNC/128)

// ---------------- scratch (static device globals; no allocation) ----------------
__device__ __align__(16) float  g_q[(size_t)NTOT*CDIM];                // raw q (fp32)
__device__ __align__(16) __half g_k16[(size_t)NTOT*CDIM];              // k (fp16)
__device__ __align__(16) __half g_v16[(size_t)NTOT*CDIM];              // v (fp16)
__device__ __align__(16) __half g_qr16[(size_t)(2*NSTMT+NFUNC)*CDIM];  // qr0|qr1|qr2 (fp16)
__device__ __align__(16) float  g_agg[(size_t)NTOT*CDIM];              // agg r0(stmt)+r1(func)
__device__ __align__(16) float  g_agg2[(size_t)NSTMT*CDIM];            // agg r2 (stmt)
__device__ __align__(16) float  g_s[(size_t)3*NSTMT*NH];               // softmax denominators
__device__ __align__(16) float  g_p2[(size_t)NTOT*CDIM];               // pooled / epilogue-prep (tf32-rounded)
__device__ __align__(16) float  g_xr[(size_t)NTOT*CDIM];               // tf32-rounded mirror of x
__device__ __align__(16) float  g_wr[(size_t)18*CC];                   // tf32-rounded weights

// ---------------- helpers ----------------
__device__ __forceinline__ float gelu_f(float x) {
    float x3 = x*x*x;
    return 0.5f*x*(1.0f + tanhf(0.7978845608028654f*(x + 0.044715f*x3)));
}
__device__ __forceinline__ float tf32r(float x) {
    unsigned u;
    asm("cvt.rna.tf32.f32 %0, %1;" : "=r"(u) : "f"(x));
    return __uint_as_float(u);
}
__device__ __forceinline__ void mma_tf32(float (&c)[4], const float* a, float b0, float b1) {
    const unsigned* A = reinterpret_cast<const unsigned*>(a);
    unsigned B0 = __float_as_uint(b0), B1 = __float_as_uint(b1);
    asm volatile("mma.sync.aligned.m16n8k8.row.col.f32.tf32.tf32.f32 "
        "{%0,%1,%2,%3}, {%4,%5,%6,%7}, {%8,%9}, {%0,%1,%2,%3};"
        : "+f"(c[0]), "+f"(c[1]), "+f"(c[2]), "+f"(c[3])
        : "r"(A[0]), "r"(A[1]), "r"(A[2]), "r"(A[3]), "r"(B0), "r"(B1));
}

// ---------------- GEMM: tf32 mma.sync, 128x128 tile, 8 warps, merged slab decode ----------------
// EPI: 0 relu (writes out fp32 + xr rounded); 1 none (HF[slab]->fp16 out);
// EPI 2: blend (writes out fp32 + xr rounded).
struct GArgs {
    const float* A0; const float* A1;
    const float* W[6]; const float* B[6];
    float* O[6];
    float* XR[6];
    const float* SK[6]; const float* X[6];
    int HF[6];
};

template<int NS0, int NS1, int EPI>
__global__ __launch_bounds__(256) void gemm_k(GArgs ga) {
    __shared__ float As[16][132];
    __shared__ float Ws[16][132];

    const int bid = blockIdx.x;
    const float* A; int M, slab, blk;
    if (NS1 == 0 || bid < NS0*NB_S) {
        slab = bid / NB_S; blk = bid - slab*NB_S; A = ga.A0; M = NSTMT;
    } else {
        int tt = bid - NS0*NB_S;
        int s1 = tt / NB_F; slab = NS0 + s1; blk = tt - s1*NB_F; A = ga.A1; M = NFUNC;
    }
    const float* __restrict__ W = ga.W[slab];
    const float* __restrict__ bias = ga.B[slab];
    float* __restrict__ out = ga.O[slab];

    const int tid  = threadIdx.x;
    const int lane = tid & 31, wid = tid >> 5;
    const int row0 = blk * 128;
    const int m0 = (wid >> 1) * 32;
    const int n0 = (wid & 1) * 64;
    const int g = lane >> 2, t = lane & 3;

    // staging indices (same as proven core)
    const int lr  = tid >> 1;
    const int lkq = (tid & 1) * 8;
    const int wk  = tid >> 4;
    const int wc  = (tid & 15) * 8;

    const int  arow = row0 + lr;
    const bool aval = arow < M;
    const float* Ap = A + (size_t)arow * CDIM + lkq;
    const float* Wp = W + (size_t)wk * CDIM + wc;

    float acc[2][8][4];
#pragma unroll
    for (int i = 0; i < 2; i++)
#pragma unroll
        for (int j = 0; j < 8; j++)
#pragma unroll
            for (int kq = 0; kq < 4; kq++) acc[i][j][kq] = 0.f;

    float4 pa0, pa1, pw0, pw1;
    const float4 z4 = make_float4(0.f, 0.f, 0.f, 0.f);

    pa0 = aval ? *reinterpret_cast<const float4*>(Ap)     : z4;
    pa1 = aval ? *reinterpret_cast<const float4*>(Ap + 4) : z4;
    pw0 = *reinterpret_cast<const float4*>(Wp);
    pw1 = *reinterpret_cast<const float4*>(Wp + 4);

#pragma unroll 1
    for (int s = 0; s < 8; s++) {
        As[lkq+0][lr] = pa0.x; As[lkq+1][lr] = pa0.y; As[lkq+2][lr] = pa0.z; As[lkq+3][lr] = pa0.w;
        As[lkq+4][lr] = pa1.x; As[lkq+5][lr] = pa1.y; As[lkq+6][lr] = pa1.z; As[lkq+7][lr] = pa1.w;
        *reinterpret_cast<float4*>(&Ws[wk][wc])     = pw0;
        *reinterpret_cast<float4*>(&Ws[wk][wc + 4]) = pw1;
        __syncthreads();

        if (s < 7) {
            int k0 = (s + 1) * 16;
            pa0 = aval ? *reinterpret_cast<const float4*>(Ap + k0)     : z4;
            pa1 = aval ? *reinterpret_cast<const float4*>(Ap + k0 + 4) : z4;
            pw0 = *reinterpret_cast<const float4*>(Wp + (size_t)k0 * CDIM);
            pw1 = *reinterpret_cast<const float4*>(Wp + (size_t)k0 * CDIM + 4);
        }

#pragma unroll
        for (int kb = 0; kb < 16; kb += 8) {
            float a[2][4];
#pragma unroll
            for (int mf = 0; mf < 2; mf++) {
                int mm = m0 + mf*16 + g;
                a[mf][0] = As[kb + t][mm];
                a[mf][1] = As[kb + t][mm + 8];
                a[mf][2] = As[kb + t + 4][mm];
                a[mf][3] = As[kb + t + 4][mm + 8];
            }
#pragma unroll
            for (int nf = 0; nf < 8; nf++) {
                int nn = n0 + nf*8 + g;
                float b0 = Ws[kb + t][nn];
                float b1 = Ws[kb + t + 4][nn];
                mma_tf32(acc[0][nf], a[0], b0, b1);
                mma_tf32(acc[1][nf], a[1], b0, b1);
            }
        }
        if (s < 7) __syncthreads();
    }

    // ---- epilogue ----
    float gg = 0.f, og = 0.f;
    const float* xold = nullptr;
    if (EPI == 2) {
        gg = 1.0f/(1.0f + expf(-*ga.SK[slab])); og = 1.0f - gg;
        xold = ga.X[slab];
    }
    const int hf = (EPI == 1) ? ga.HF[slab] : 0;
    float* xr = (EPI != 1) ? ga.XR[slab] : nullptr;

#pragma unroll
    for (int mf = 0; mf < 2; mf++) {
#pragma unroll
        for (int h8 = 0; h8 < 2; h8++) {
            int row = row0 + m0 + mf*16 + g + h8*8;
            if (row >= M) continue;
#pragma unroll
            for (int nf = 0; nf < 8; nf++) {
                int col = n0 + nf*8 + 2*t;
                float2 bb = *reinterpret_cast<const float2*>(&bias[col]);
                float v0 = acc[mf][nf][h8*2 + 0] + bb.x;
                float v1 = acc[mf][nf][h8*2 + 1] + bb.y;
                if (EPI == 0) { v0 = fmaxf(v0, 0.f); v1 = fmaxf(v1, 0.f); }
                if (EPI == 2) {
                    float2 xo = *reinterpret_cast<const float2*>(&xold[(size_t)row*CDIM + col]);
                    v0 = gg*v0 + og*xo.x; v1 = gg*v1 + og*xo.y;
                }
                if (EPI == 1 && hf) {
                    __half2 hh = __floats2half2_rn(v0, v1);
                    *reinterpret_cast<__half2*>(
                        reinterpret_cast<__half*>(out) + (size_t)row*CDIM + col) = hh;
                } else {
                    *reinterpret_cast<float2*>(&out[(size_t)row*CDIM + col]) = make_float2(v0, v1);
                }
                if (EPI != 1) {
                    *reinterpret_cast<float2*>(&xr[(size_t)row*CDIM + col]) =
                        make_float2(tf32r(v0), tf32r(v1));
                }
            }
        }
    }
}

// ---------------- weight prep: tf32 rounding ----------------
struct WPrep { const float* s[18]; };
__global__ void prepw_k(WPrep wp) {
    int idx = blockIdx.x*blockDim.x + threadIdx.x;
    int m = idx >> 14;
    if (m >= 18) return;
    int o = idx & 16383;
    g_wr[(size_t)m*CC + o] = tf32r(wp.s[m][o]);
}

// ---------------- small kernels ----------------
__global__ void pool_k(const int* __restrict__ tok, const float* __restrict__ emb,
                       float* __restrict__ out, int N) {
    int node = blockIdx.x*2 + (threadIdx.x >> 7);
    int c = threadIdx.x & 127;
    if (node >= N) return;
    const int* tp = tok + (size_t)node*NTOK;
    float s = 0.f;
#pragma unroll
    for (int t = 0; t < NTOK; t++) s += emb[(size_t)tp[t]*CDIM + c];
    s *= (1.0f/NTOK);
    out[(size_t)node*CDIM + c] = tf32r(s > 0.f ? s : 0.f);
}

// qr[n,h,d] = p_rel[h]*scale * sum_e q[n,h,e] * a_rel[h,d,e]  -> fp16 out
__global__ __launch_bounds__(256) void qr_k(const float* __restrict__ q,
        const float* __restrict__ a_rel, const float* __restrict__ p_rel,
        __half* __restrict__ qrout, int l) {
    const int r = blockIdx.y;
    const int N = (r == 1) ? NFUNC : NSTMT;
    const int node0 = blockIdx.x * 32;
    if (node0 >= N) return;
    const float* qg = q + ((r == 1) ? (size_t)NSTMT*CDIM : 0);
    __half* out;
    if (r == 0)      out = qrout;
    else if (r == 1) out = qrout + (size_t)NSTMT*CDIM;
    else             out = qrout + (size_t)NSTMT*CDIM + (size_t)NFUNC*CDIM;

    __shared__ float qs[32][128];
    const int tid = threadIdx.x;
    for (int i = tid; i < 1024; i += 256) {
        int row = i >> 5, c4 = i & 31;
        float4 vv = make_float4(0.f,0.f,0.f,0.f);
        if (node0 + row < N)
            vv = reinterpret_cast<const float4*>(qg + (size_t)(node0+row)*CDIM)[c4];
        reinterpret_cast<float4*>(&qs[row][0])[c4] = vv;
    }
    const int c = tid & 127, h = c >> 4, d = c & 15;
    const float* Ab = a_rel + (((size_t)(l*3 + r)*NH + h)*HD + d)*HD;
    float4 a0 = reinterpret_cast<const float4*>(Ab)[0];
    float4 a1 = reinterpret_cast<const float4*>(Ab)[1];
    float4 a2 = reinterpret_cast<const float4*>(Ab)[2];
    float4 a3 = reinterpret_cast<const float4*>(Ab)[3];
    const float ps = p_rel[(l*3 + r)*NH + h] * 0.25f;
    __syncthreads();

    const int half_ = tid >> 7;
#pragma unroll 4
    for (int ni = 0; ni < 16; ni++) {
        int node = node0 + half_*16 + ni;
        if (node >= N) break;
        const float4* q4 = reinterpret_cast<const float4*>(&qs[half_*16 + ni][h*HD]);
        float4 q0 = q4[0], q1 = q4[1], q2 = q4[2], q3 = q4[3];
        float s = a0.x*q0.x + a0.y*q0.y + a0.z*q0.z + a0.w*q0.w
                + a1.x*q1.x + a1.y*q1.y + a1.z*q1.z + a1.w*q1.w
                + a2.x*q2.x + a2.y*q2.y + a2.z*q2.z + a2.w*q2.w
                + a3.x*q3.x + a3.y*q3.y + a3.z*q3.z + a3.w*q3.w;
        out[(size_t)node*CDIM + c] = __float2half(s * ps);
    }
}

// epilogue prep: P[n,h,e] = tf32( gelu( sum_d agg0[n,h,d]*M0[h,d,e]/s0 [+ agg2.../s2] ) )
template<int NR>
__global__ __launch_bounds__(256) void aggprep_k(const float* __restrict__ agg0,
        const float* __restrict__ agg2, const float* __restrict__ s0,
        const float* __restrict__ s2, const float* __restrict__ M0g,
        const float* __restrict__ M2g, float* __restrict__ P, int N) {
    __shared__ float as0[32][128];
    __shared__ float as2[NR == 2 ? 32 : 1][NR == 2 ? 128 : 4];
    const int node0 = blockIdx.x * 32;
    if (node0 >= N) return;
    const int tid = threadIdx.x;
    for (int i = tid; i < 1024; i += 256) {
        int row = i >> 5, c4 = i & 31;
        bool pr = node0 + row < N;
        float4 z = make_float4(0.f,0.f,0.f,0.f);
        reinterpret_cast<float4*>(&as0[row][0])[c4] =
            pr ? reinterpret_cast<const float4*>(agg0 + (size_t)(node0+row)*CDIM)[c4] : z;
        if (NR == 2)
            reinterpret_cast<float4*>(&as2[row][0])[c4] =
                pr ? reinterpret_cast<const float4*>(agg2 + (size_t)(node0+row)*CDIM)[c4] : z;
    }
    const int c = tid & 127, h = c >> 4, e = c & 15;
    float m0[16], m2[16];
#pragma unroll
    for (int d = 0; d < 16; d++) {
        m0[d] = M0g[((size_t)h*HD + d)*HD + e];
        if (NR == 2) m2[d] = M2g[((size_t)h*HD + d)*HD + e];
    }
    __syncthreads();

    const int half_ = tid >> 7;
#pragma unroll 2
    for (int ni = 0; ni < 16; ni++) {
        int node = node0 + half_*16 + ni;
        if (node >= N) break;
        float w0 = 1.0f / (s0[(size_t)node*NH + h] + 1e-16f);
        const float* ar = &as0[half_*16 + ni][h*HD];
        float t0 = 0.f;
#pragma unroll
        for (int d = 0; d < 16; d++) t0 += ar[d]*m0[d];
        float v = t0 * w0;
        if (NR == 2) {
            float w2 = 1.0f / (s2[(size_t)node*NH + h] + 1e-16f);
            const float* ar2 = &as2[half_*16 + ni][h*HD];
            float t2 = 0.f;
#pragma unroll
            for (int d = 0; d < 16; d++) t2 += ar2[d]*m2[d];
            v += t2 * w2;
        }
        P[(size_t)node*CDIM + c] = tf32r(gelu_f(v));
    }
}

// ---------------- fused edge kernel: 2 edges/warp, batched gathers ----------------
struct EdgeArgs {
    const int*    src[3];
    const int*    dst[3];
    const __half* qr[3];
    const __half* k[3];
    const __half* v[3];
    float*        sb[3];
    float*        agg[3];
};

__device__ __forceinline__ float h4dot(uint2 a, uint2 b) {
    __half2 a0 = *reinterpret_cast<__half2*>(&a.x);
    __half2 a1 = *reinterpret_cast<__half2*>(&a.y);
    __half2 b0 = *reinterpret_cast<__half2*>(&b.x);
    __half2 b1 = *reinterpret_cast<__half2*>(&b.y);
    float2 fa0 = __half22float2(a0), fa1 = __half22float2(a1);
    float2 fb0 = __half22float2(b0), fb1 = __half22float2(b1);
    return fa0.x*fb0.x + fa0.y*fb0.y + fa1.x*fb1.x + fa1.y*fb1.y;
}
__device__ __forceinline__ float4 h4scale(uint2 u, float s) {
    __half2 h0 = *reinterpret_cast<__half2*>(&u.x);
    __half2 h1 = *reinterpret_cast<__half2*>(&u.y);
    float2 f0 = __half22float2(h0), f1 = __half22float2(h1);
    return make_float4(f0.x*s, f0.y*s, f1.x*s, f1.y*s);
}

__global__ void edge_k(EdgeArgs ea, int ne2) {   // ne2 = NE/2 warps
    int w = (blockIdx.x*blockDim.x + threadIdx.x) >> 5;
    int lane = threadIdx.x & 31;
    if (w >= ne2) return;
    int r = blockIdx.y;
    int e0 = w*2, e1 = e0 + 1;
    int s0 = ea.src[r][e0], d0 = ea.dst[r][e0];
    int s1 = ea.src[r][e1], d1 = ea.dst[r][e1];
    const size_t off = (size_t)lane*4;
    uint2 qu0 = *reinterpret_cast<const uint2*>(ea.qr[r] + (size_t)d0*CDIM + off);
    uint2 ku0 = *reinterpret_cast<const uint2*>(ea.k[r]  + (size_t)s0*CDIM + off);
    uint2 qu1 = *reinterpret_cast<const uint2*>(ea.qr[r] + (size_t)d1*CDIM + off);
    uint2 ku1 = *reinterpret_cast<const uint2*>(ea.k[r]  + (size_t)s1*CDIM + off);
    uint2 vu0 = *reinterpret_cast<const uint2*>(ea.v[r]  + (size_t)s0*CDIM + off);
    uint2 vu1 = *reinterpret_cast<const uint2*>(ea.v[r]  + (size_t)s1*CDIM + off);

    float p0 = h4dot(qu0, ku0);
    float p1 = h4dot(qu1, ku1);
    p0 += __shfl_xor_sync(0xffffffffu, p0, 1);
    p1 += __shfl_xor_sync(0xffffffffu, p1, 1);
    p0 += __shfl_xor_sync(0xffffffffu, p0, 2);
    p1 += __shfl_xor_sync(0xffffffffu, p1, 2);
    float ev0 = __expf(p0);
    float ev1 = __expf(p1);
    int h = lane >> 2;
    if ((lane & 3) == 0) {
        atomicAdd(ea.sb[r] + (size_t)d0*NH + h, ev0);
        atomicAdd(ea.sb[r] + (size_t)d1*NH + h, ev1);
    }
    float4 m0 = h4scale(vu0, ev0);
    float4 m1 = h4scale(vu1, ev1);
    atomicAdd(reinterpret_cast<float4*>(ea.agg[r] + (size_t)d0*CDIM + off), m0);
    atomicAdd(reinterpret_cast<float4*>(ea.agg[r] + (size_t)d1*CDIM + off), m1);
}

// ---------------- host launcher ----------------
extern "C" void kernel_launch(void* const* d_in, const int* in_sizes, int n_in,
                              void* d_out, int out_size) {
    const int* tok_stmt = (const int*)d_in[0];
    const int* tok_func = (const int*)d_in[1];
    const int* esrc[3] = {(const int*)d_in[2], (const int*)d_in[4], (const int*)d_in[6]};
    const int* edst[3] = {(const int*)d_in[3], (const int*)d_in[5], (const int*)d_in[7]};
    const float* emb   = (const float*)d_in[8];
    const float* lin_w = (const float*)d_in[9];
    const float* lin_b = (const float*)d_in[10];
    const float* kw = (const float*)d_in[11];
    const float* kb = (const float*)d_in[12];
    const float* qw = (const float*)d_in[13];
    const float* qb = (const float*)d_in[14];
    const float* vw = (const float*)d_in[15];
    const float* vb = (const float*)d_in[16];
    const float* aw = (const float*)d_in[17];
    const float* ab = (const float*)d_in[18];
    const float* skip  = (const float*)d_in[19];
    const float* a_rel = (const float*)d_in[20];
    const float* m_rel = (const float*)d_in[21];
    const float* p_rel = (const float*)d_in[22];
    float* x = (float*)d_out;

    float *q, *agg, *agg2, *sbuf, *p2, *xr, *wr;
    __half *k16, *v16, *qr16;
    cudaGetSymbolAddress((void**)&q,    g_q);
    cudaGetSymbolAddress((void**)&k16,  g_k16);
    cudaGetSymbolAddress((void**)&v16,  g_v16);
    cudaGetSymbolAddress((void**)&qr16, g_qr16);
    cudaGetSymbolAddress((void**)&agg,  g_agg);
    cudaGetSymbolAddress((void**)&agg2, g_agg2);
    cudaGetSymbolAddress((void**)&sbuf, g_s);
    cudaGetSymbolAddress((void**)&p2,   g_p2);
    cudaGetSymbolAddress((void**)&xr,   g_xr);
    cudaGetSymbolAddress((void**)&wr,   g_wr);

    const size_t XF  = (size_t)NSTMT*CDIM;
    const size_t QF2 = XF + (size_t)NFUNC*CDIM;

    // ---- weight prep: tf32-round all 18 matrices once ----
    {
        WPrep wp{};
        wp.s[0] = lin_w; wp.s[1] = lin_w + CC;
        for (int l = 0; l < 2; l++) {
            int b = 2 + l*8;
            wp.s[b+0] = qw + (size_t)(l*2+0)*CC;
            wp.s[b+1] = kw + (size_t)(l*2+0)*CC;
            wp.s[b+2] = vw + (size_t)(l*2+0)*CC;
            wp.s[b+3] = qw + (size_t)(l*2+1)*CC;
            wp.s[b+4] = kw + (size_t)(l*2+1)*CC;
            wp.s[b+5] = vw + (size_t)(l*2+1)*CC;
            wp.s[b+6] = aw + (size_t)(l*2+0)*CC;
            wp.s[b+7] = aw + (size_t)(l*2+1)*CC;
        }
        prepw_k<<<(18*16384 + 255)/256, 256>>>(wp);
    }

    // ---- encoder: pool(tf32) + per-type linear + relu ----
    pool_k<<<(NSTMT+1)/2, 256>>>(tok_stmt, emb, p2, NSTMT);
    pool_k<<<(NFUNC+1)/2, 256>>>(tok_func, emb, p2 + XF, NFUNC);
    {
        GArgs ga{};
        ga.A0 = p2; ga.A1 = p2 + XF;
        ga.W[0] = wr;      ga.B[0] = lin_b;        ga.O[0] = x;      ga.XR[0] = xr;
        ga.W[1] = wr + CC; ga.B[1] = lin_b + CDIM; ga.O[1] = x + XF; ga.XR[1] = xr + XF;
        gemm_k<1,1,0><<<NB_S + NB_F, 256>>>(ga);
    }

    for (int l = 0; l < 2; l++) {
        const float* wl = wr + (size_t)(2 + l*8)*CC;
        // raw projections, merged: stmt [q,k16,v16], func [q,k16,v16] (A = xr)
        {
            GArgs ga{};
            ga.A0 = xr; ga.A1 = xr + XF;
            ga.W[0] = wl + 0*(size_t)CC; ga.B[0] = qb + (size_t)(l*2+0)*CDIM;
            ga.O[0] = q;                  ga.HF[0] = 0;
            ga.W[1] = wl + 1*(size_t)CC; ga.B[1] = kb + (size_t)(l*2+0)*CDIM;
            ga.O[1] = (float*)k16;        ga.HF[1] = 1;
            ga.W[2] = wl + 2*(size_t)CC; ga.B[2] = vb + (size_t)(l*2+0)*CDIM;
            ga.O[2] = (float*)v16;        ga.HF[2] = 1;
            ga.W[3] = wl + 3*(size_t)CC; ga.B[3] = qb + (size_t)(l*2+1)*CDIM;
            ga.O[3] = q + XF;             ga.HF[3] = 0;
            ga.W[4] = wl + 4*(size_t)CC; ga.B[4] = kb + (size_t)(l*2+1)*CDIM;
            ga.O[4] = (float*)(k16 + XF); ga.HF[4] = 1;
            ga.W[5] = wl + 5*(size_t)CC; ga.B[5] = vb + (size_t)(l*2+1)*CDIM;
            ga.O[5] = (float*)(v16 + XF); ga.HF[5] = 1;
            gemm_k<3,3,1><<<3*NB_S + 3*NB_F, 256>>>(ga);
        }

        // qr = dst-side a_rel fold -> fp16 (3 relations in one launch)
        qr_k<<<dim3((NSTMT + 31)/32, 3), 256>>>(q, a_rel, p_rel, qr16, l);

        cudaMemsetAsync(agg,  0, (size_t)NTOT*CDIM*sizeof(float), 0);
        cudaMemsetAsync(agg2, 0, (size_t)NSTMT*CDIM*sizeof(float), 0);
        cudaMemsetAsync(sbuf, 0, (size_t)3*NSTMT*NH*sizeof(float), 0);

        EdgeArgs ea;
        const __half* qroff[3] = {qr16, qr16 + XF, qr16 + QF2};
        for (int r = 0; r < 3; r++) {
            ea.src[r] = esrc[r]; ea.dst[r] = edst[r];
            ea.qr[r] = qroff[r];
            ea.k[r]  = k16 + ((r == 2) ? XF : 0);
            ea.v[r]  = v16 + ((r == 2) ? XF : 0);
            ea.sb[r] = sbuf + (size_t)r*NSTMT*NH;
        }
        ea.agg[0] = agg;
        ea.agg[1] = agg + XF;
        ea.agg[2] = agg2;
        edge_k<<<dim3((NE/2*32 + 255)/256, 3), 256>>>(ea, NE/2);

        // epilogue prep: P = tf32(gelu( m_rel-transform + normalize ))
        const float* M0 = m_rel + (size_t)(l*3 + 0)*NH*HD*HD;
        const float* M1 = m_rel + (size_t)(l*3 + 1)*NH*HD*HD;
        const float* M2 = m_rel + (size_t)(l*3 + 2)*NH*HD*HD;
        aggprep_k<2><<<(NSTMT + 31)/32, 256>>>(agg, agg2,
            sbuf + 0*(size_t)NSTMT*NH, sbuf + 2*(size_t)NSTMT*NH, M0, M2, p2, NSTMT);
        aggprep_k<1><<<(NFUNC + 31)/32, 256>>>(agg + XF, nullptr,
            sbuf + 1*(size_t)NSTMT*NH, nullptr, M1, nullptr, p2 + XF, NFUNC);

        // merged epilogue: x = g*(P @ aw + ab) + (1-g)*x ; refresh xr
        {
            GArgs ga{};
            ga.A0 = p2; ga.A1 = p2 + XF;
            ga.W[0] = wl + 6*(size_t)CC; ga.B[0] = ab + (size_t)(l*2+0)*CDIM;
            ga.O[0] = x;      ga.XR[0] = xr;      ga.SK[0] = skip + l*2 + 0; ga.X[0] = x;
            ga.W[1] = wl + 7*(size_t)CC; ga.B[1] = ab + (size_t)(l*2+1)*CDIM;
            ga.O[1] = x + XF; ga.XR[1] = xr + XF; ga.SK[1] = skip + l*2 + 1; ga.X[1] = x + XF;
            gemm_k<1,1,2><<<NB_S + NB_F, 256>>>(ga);
        }
    }
}